// round 2
// baseline (speedup 1.0000x reference)
#include <cuda_runtime.h>

#define BB 4
#define NN 16384
#define CC 256
#define HH 8
#define DD 64
#define HD 512
#define OUTC 256
#define NC 16            // N-chunks (split-K over the grid axis)
#define CH 1024          // tokens per chunk
#define TT 64            // tokens per inner tile

// scratch (static device globals; ~11 MB total)
__device__ float g_kvp[NC*BB*HH*DD*DD];     // split-K partials of k^T v
__device__ float g_sump[NC*BB*HH*4*DD];     // [chunk][bh][ksum|ksq|vsum|vsq][64]
__device__ float g_T[BB*CC*HD];             // Wq_h^T @ kvhat, [b][c][h*64+e]
__device__ float g_F[BB*CC*OUTC];           // fused right-hand matrix per batch

// ---------------------------------------------------------------------------
// K12 (fused): for block (chunk, h, b), stream 64-token tiles of U, compute
// k|v = U_tile @ [Wk_h|Wv_h]^T into smem, accumulate k^T v (64x64) partials
// and column sums / sums-of-squares in registers. No k/v materialization.
// 256 threads; GEMM tile 64 tokens x 128 cols, 8x k-step, 4x8 reg tile.
// ---------------------------------------------------------------------------
__global__ __launch_bounds__(256) void k12_proj_kv(const float* __restrict__ U,
                                                   const float* __restrict__ Wk,
                                                   const float* __restrict__ Wv) {
    __shared__ float As[8][68];      // [k][token]
    __shared__ float Bs[8][132];     // [k][col]  col 0..63 = k-head, 64..127 = v-head
    __shared__ float KVs[TT][136];   // [token][col] projected tile

    const int chunk = blockIdx.x;
    const int h     = blockIdx.y;
    const int b     = blockIdx.z;
    const int bh    = b * HH + h;
    const int tid   = threadIdx.x;
    const int tx    = tid & 15;      // col group (8 cols)
    const int ty    = tid >> 4;      // token group (4 tokens)

    // per-thread constant W row for Bs loading
    const int wc   = tid >> 1;             // 0..127
    const int wp   = (tid & 1) * 4;        // 0 or 4
    const float* Wrow = (wc < DD)
        ? (Wk + (size_t)(h * DD + wc) * CC + wp)
        : (Wv + (size_t)(h * DD + (wc - DD)) * CC + wp);

    const int atok = tid >> 1;             // 0..127 (valid token if tid<128)
    const int ap   = (tid & 1) * 4;

    float kvacc[4][4];
    #pragma unroll
    for (int i = 0; i < 4; i++) {
        #pragma unroll
        for (int j = 0; j < 4; j++) kvacc[i][j] = 0.f;
    }
    float s = 0.f, sq = 0.f;

    const float* Uc = U + (size_t)(b * NN + chunk * CH) * CC;

    for (int t0 = 0; t0 < CH; t0 += TT) {
        const float* Ut = Uc + (size_t)t0 * CC;

        float acc[4][8];
        #pragma unroll
        for (int i = 0; i < 4; i++) {
            #pragma unroll
            for (int j = 0; j < 8; j++) acc[i][j] = 0.f;
        }

        for (int kt = 0; kt < CC; kt += 8) {
            if (tid < 128) {
                float4 a = *(const float4*)(Ut + (size_t)atok * CC + kt + ap);
                As[ap+0][atok] = a.x; As[ap+1][atok] = a.y;
                As[ap+2][atok] = a.z; As[ap+3][atok] = a.w;
            }
            float4 w = *(const float4*)(Wrow + kt);
            Bs[wp+0][wc] = w.x; Bs[wp+1][wc] = w.y;
            Bs[wp+2][wc] = w.z; Bs[wp+3][wc] = w.w;
            __syncthreads();
            #pragma unroll
            for (int k = 0; k < 8; ++k) {
                float4 a4 = *(const float4*)&As[k][ty*4];
                float4 b0 = *(const float4*)&Bs[k][tx*8];
                float4 b1 = *(const float4*)&Bs[k][tx*8+4];
                float aa[4] = {a4.x, a4.y, a4.z, a4.w};
                float bb[8] = {b0.x, b0.y, b0.z, b0.w, b1.x, b1.y, b1.z, b1.w};
                #pragma unroll
                for (int i = 0; i < 4; i++) {
                    #pragma unroll
                    for (int j = 0; j < 8; j++)
                        acc[i][j] = fmaf(aa[i], bb[j], acc[i][j]);
                }
            }
            __syncthreads();
        }

        // stash projected tile to smem
        #pragma unroll
        for (int i = 0; i < 4; i++) {
            const int t = ty * 4 + i;
            *(float4*)&KVs[t][tx*8]   = make_float4(acc[i][0], acc[i][1], acc[i][2], acc[i][3]);
            *(float4*)&KVs[t][tx*8+4] = make_float4(acc[i][4], acc[i][5], acc[i][6], acc[i][7]);
        }
        __syncthreads();

        // outer-product accumulate: kv[d][e] += k[t][d] * v[t][e]
        #pragma unroll 8
        for (int t = 0; t < TT; t++) {
            float4 kk4 = *(const float4*)&KVs[t][ty*4];
            float4 vv4 = *(const float4*)&KVs[t][64 + tx*4];
            float kk[4] = {kk4.x, kk4.y, kk4.z, kk4.w};
            float vv[4] = {vv4.x, vv4.y, vv4.z, vv4.w};
            #pragma unroll
            for (int i = 0; i < 4; i++) {
                #pragma unroll
                for (int j = 0; j < 4; j++)
                    kvacc[i][j] = fmaf(kk[i], vv[j], kvacc[i][j]);
            }
        }
        // column sums / sumsq (threads 0..127, one column each)
        if (tid < 128) {
            #pragma unroll 8
            for (int t = 0; t < TT; t++) {
                float x = KVs[t][tid];
                s += x; sq = fmaf(x, x, sq);
            }
        }
        __syncthreads();
    }

    float* op = g_kvp + (size_t)(chunk * BB * HH + bh) * DD * DD;
    #pragma unroll
    for (int i = 0; i < 4; i++) {
        #pragma unroll
        for (int j = 0; j < 4; j++)
            op[(ty*4 + i) * DD + tx*4 + j] = kvacc[i][j];
    }
    float* sp = g_sump + (size_t)(chunk * BB * HH + bh) * 4 * DD;
    if (tid < DD)            { sp[tid] = s;               sp[DD + tid] = sq; }
    else if (tid < 2*DD)     { sp[2*DD + (tid-DD)] = s;   sp[3*DD + (tid-DD)] = sq; }
}

// ---------------------------------------------------------------------------
// K3: finalize stats -> kvhat (in smem) -> T[b][c][h*64+e] = sum_d Wq[hD+d][c]*kvhat[d][e]
// grid B*H, 256 threads (thread = output channel c).
// ---------------------------------------------------------------------------
__global__ __launch_bounds__(256) void k3_T(const float* __restrict__ Wq) {
    __shared__ float mk[64], rk[64], mv[64], rv[64];
    __shared__ float kvs[64][64];
    const int bh = blockIdx.x;
    const int b = bh >> 3, h = bh & 7;
    const int tid = threadIdx.x;
    const float invN = 1.f / NN;

    if (tid < 64) {
        float s = 0, sqv = 0, s2 = 0, sq2 = 0;
        for (int ch = 0; ch < NC; ch++) {
            const float* sp = g_sump + (size_t)(ch * BB * HH + bh) * 4 * DD;
            s += sp[tid]; sqv += sp[64 + tid]; s2 += sp[128 + tid]; sq2 += sp[192 + tid];
        }
        float m = s * invN;  mk[tid] = m;  rk[tid] = rsqrtf(sqv * invN - m * m + 1e-5f);
        float m2 = s2 * invN; mv[tid] = m2; rv[tid] = rsqrtf(sq2 * invN - m2 * m2 + 1e-5f);
    }
    __syncthreads();

    for (int idx = tid; idx < DD * DD; idx += 256) {
        float sum = 0.f;
        for (int ch = 0; ch < NC; ch++)
            sum += g_kvp[(size_t)(ch * BB * HH + bh) * DD * DD + idx];
        const int d = idx >> 6, e = idx & 63;
        kvs[d][e] = rk[d] * rv[e] * (sum * invN - mk[d] * mv[e]);
    }
    __syncthreads();

    float accT[64];
    #pragma unroll
    for (int e = 0; e < 64; e++) accT[e] = 0.f;
    const int c = tid;
    for (int d = 0; d < DD; d++) {
        const float wq = Wq[(size_t)(h * DD + d) * CC + c];
        #pragma unroll
        for (int e4 = 0; e4 < 16; e4++) {
            float4 t = *(const float4*)&kvs[d][e4 * 4];
            accT[e4*4+0] = fmaf(wq, t.x, accT[e4*4+0]);
            accT[e4*4+1] = fmaf(wq, t.y, accT[e4*4+1]);
            accT[e4*4+2] = fmaf(wq, t.z, accT[e4*4+2]);
            accT[e4*4+3] = fmaf(wq, t.w, accT[e4*4+3]);
        }
    }
    float* Tp = g_T + ((size_t)b * CC + c) * HD + h * DD;
    #pragma unroll
    for (int e = 0; e < 64; e++) Tp[e] = accT[e];
}

// ---------------------------------------------------------------------------
// K3c: F[b] (256x256) = T[b] (256x512) @ Wo^T (Wo is [256,512] row-major).
// grid (16 o-tiles, 16 c-tiles, B), 16x16 threads, one output each.
// ---------------------------------------------------------------------------
__global__ __launch_bounds__(256) void k3c_F(const float* __restrict__ Wo) {
    __shared__ float Ts[16][32];
    __shared__ float Wos[16][34];
    const int o0 = blockIdx.x * 16;
    const int c0 = blockIdx.y * 16;
    const int b  = blockIdx.z;
    const int tid = threadIdx.x;
    const int tx = tid & 15, ty = tid >> 4;
    const int lr  = tid >> 4;           // 0..15
    const int lc2 = (tid & 15) * 2;     // 0..30
    float acc = 0.f;
    for (int j0 = 0; j0 < HD; j0 += 32) {
        float2 t = *(const float2*)&g_T[((size_t)b * CC + c0 + lr) * HD + j0 + lc2];
        Ts[lr][lc2] = t.x; Ts[lr][lc2 + 1] = t.y;
        float2 w = *(const float2*)&Wo[(size_t)(o0 + lr) * HD + j0 + lc2];
        Wos[lr][lc2] = w.x; Wos[lr][lc2 + 1] = w.y;
        __syncthreads();
        #pragma unroll
        for (int j = 0; j < 32; j++) acc = fmaf(Ts[ty][j], Wos[tx][j], acc);
        __syncthreads();
    }
    g_F[((size_t)b * CC + c0 + ty) * OUTC + o0 + tx] = acc;
}

// ---------------------------------------------------------------------------
// K4: out[token][o] = sum_c U[token][c] * F[b][c][o] + bo[o]
// 128x128x8 sgemm skeleton; B operand already [K x N] row-major.
// ---------------------------------------------------------------------------
__global__ __launch_bounds__(256) void k4_out(const float* __restrict__ U,
                                              const float* __restrict__ bo,
                                              float* __restrict__ out) {
    __shared__ float As[8][132];
    __shared__ float Bs[8][132];
    const int ot0 = blockIdx.x * 128;   // 0 or 128
    const int mt0 = blockIdx.y * 128;
    const int b = mt0 >> 14;
    const float* Fp = g_F + (size_t)b * CC * OUTC;
    const int tid = threadIdx.x;
    const int tx = tid & 15, ty = tid >> 4;
    const int lrow = tid >> 1;
    const int lk4  = (tid & 1) * 4;
    const int brow = tid >> 5;          // 0..7
    const int bc4  = (tid & 31) * 4;    // 0..124

    float acc[8][8];
    #pragma unroll
    for (int i = 0; i < 8; i++) {
        #pragma unroll
        for (int j = 0; j < 8; j++) acc[i][j] = 0.f;
    }

    const float* Arow = U + (size_t)(mt0 + lrow) * CC + lk4;

    for (int kt = 0; kt < CC; kt += 8) {
        float4 a = *(const float4*)(Arow + kt);
        As[lk4+0][lrow] = a.x; As[lk4+1][lrow] = a.y;
        As[lk4+2][lrow] = a.z; As[lk4+3][lrow] = a.w;
        float4 f = *(const float4*)&Fp[(size_t)(kt + brow) * OUTC + ot0 + bc4];
        *(float4*)&Bs[brow][bc4] = f;
        __syncthreads();
        #pragma unroll
        for (int k = 0; k < 8; ++k) {
            float a8[8], b8[8];
            *(float4*)&a8[0] = *(const float4*)&As[k][ty*8];
            *(float4*)&a8[4] = *(const float4*)&As[k][ty*8+4];
            *(float4*)&b8[0] = *(const float4*)&Bs[k][tx*8];
            *(float4*)&b8[4] = *(const float4*)&Bs[k][tx*8+4];
            #pragma unroll
            for (int i = 0; i < 8; i++) {
                #pragma unroll
                for (int j = 0; j < 8; j++)
                    acc[i][j] = fmaf(a8[i], b8[j], acc[i][j]);
            }
        }
        __syncthreads();
    }

    float bias[8];
    #pragma unroll
    for (int j = 0; j < 8; j++) bias[j] = bo[ot0 + tx*8 + j];
    #pragma unroll
    for (int i = 0; i < 8; i++) {
        const int token = mt0 + ty * 8 + i;
        float* orow = out + (size_t)token * OUTC + ot0 + tx * 8;
        #pragma unroll
        for (int j = 0; j < 8; j++) orow[j] = acc[i][j] + bias[j];
    }
}

// ---------------------------------------------------------------------------
extern "C" void kernel_launch(void* const* d_in, const int* in_sizes, int n_in,
                              void* d_out, int out_size) {
    const float* u  = (const float*)d_in[0];
    // d_in[1] = pos_src -- unused by the reference computation
    const float* Wq = (const float*)d_in[2];
    const float* Wk = (const float*)d_in[3];
    const float* Wv = (const float*)d_in[4];
    const float* Wo = (const float*)d_in[5];
    const float* bo = (const float*)d_in[6];
    float* out = (float*)d_out;

    k12_proj_kv<<<dim3(NC, HH, BB), 256>>>(u, Wk, Wv);
    k3_T<<<BB * HH, 256>>>(Wq);
    k3c_F<<<dim3(16, 16, BB), 256>>>(Wo);
    k4_out<<<dim3(2, 512), 256>>>(u, bo, out);
}

// round 3
// speedup vs baseline: 2.9774x; 2.9774x over previous
#include <cuda_runtime.h>

#define BB 4
#define NN 16384
#define CC 256
#define HH 8
#define DD 64
#define HD 512
#define OUTC 256
#define NCH 32           // split-K chunks over the grid axis for G
#define KCH 512          // tokens per chunk

// static device scratch (~42 MB)
__device__ float g_Gp[BB*NCH*CC*CC];     // per-chunk partials of G = U^T U
__device__ float g_sup[BB*NCH*CC];       // per-chunk column sums of U
__device__ float g_G[BB*CC*CC];          // reduced Gram matrices
__device__ float g_su[BB*CC];            // reduced column sums
__device__ float g_P[2*BB*HH*DD*CC];     // P[leg][bh] = W_h @ G   (64 x 256)
__device__ float g_kvhat[BB*HH*DD*DD];   // normalized kv matrices
__device__ float g_T[BB*CC*HD];          // Wq_h^T @ kvhat, [b][c][h*64+e]
__device__ float g_F[BB*CC*OUTC];        // fused right-hand matrix per batch

// ---------------------------------------------------------------------------
// k_g: split-K syrk partials. block = (tile 2x2 of 128x128, chunk, batch).
// G_p[b,ch] += U[b, ch-rows]^T U[b, ch-rows]. Tokens are the K dimension.
// ---------------------------------------------------------------------------
__global__ __launch_bounds__(256) void k_g(const float* __restrict__ U) {
    __shared__ float Us[8][264];
    const int tile = blockIdx.x;            // 0..3
    const int ti = tile >> 1, tj = tile & 1;
    const int ch = blockIdx.y, b = blockIdx.z;
    const int tid = threadIdx.x;
    const int tx = tid & 15, ty = tid >> 4;

    const int row0 = tid >> 6,       c0 = (tid & 63) * 4;
    const int row1 = (tid + 256) >> 6, c1 = (tid & 63) * 4;   // rows 4..7

    const float* Up = U + (size_t)(b * NN + ch * KCH) * CC;

    float acc[8][8];
    #pragma unroll
    for (int i = 0; i < 8; i++) {
        #pragma unroll
        for (int j = 0; j < 8; j++) acc[i][j] = 0.f;
    }
    float s = 0.f;

    for (int t0 = 0; t0 < KCH; t0 += 8) {
        const float* Ut = Up + (size_t)t0 * CC;
        float4 a0 = *(const float4*)(Ut + (size_t)row0 * CC + c0);
        float4 a1 = *(const float4*)(Ut + (size_t)row1 * CC + c1);
        *(float4*)&Us[row0][c0] = a0;
        *(float4*)&Us[row1][c1] = a1;
        __syncthreads();
        #pragma unroll
        for (int kk = 0; kk < 8; kk++) {
            float a8[8], b8[8];
            *(float4*)&a8[0] = *(const float4*)&Us[kk][ti*128 + ty*8];
            *(float4*)&a8[4] = *(const float4*)&Us[kk][ti*128 + ty*8 + 4];
            *(float4*)&b8[0] = *(const float4*)&Us[kk][tj*128 + tx*8];
            *(float4*)&b8[4] = *(const float4*)&Us[kk][tj*128 + tx*8 + 4];
            #pragma unroll
            for (int i = 0; i < 8; i++) {
                #pragma unroll
                for (int j = 0; j < 8; j++)
                    acc[i][j] = fmaf(a8[i], b8[j], acc[i][j]);
            }
        }
        if (tile == 0) {
            #pragma unroll
            for (int kk = 0; kk < 8; kk++) s += Us[kk][tid];
        }
        __syncthreads();
    }

    float* op = g_Gp + (size_t)(b * NCH + ch) * CC * CC;
    #pragma unroll
    for (int i = 0; i < 8; i++) {
        float* orow = op + (size_t)(ti*128 + ty*8 + i) * CC + tj*128 + tx*8;
        #pragma unroll
        for (int j = 0; j < 8; j++) orow[j] = acc[i][j];
    }
    if (tile == 0) g_sup[(size_t)(b * NCH + ch) * CC + tid] = s;
}

// ---------------------------------------------------------------------------
// kA: reduce split-K partials -> g_G, g_su. block = (row, batch), thread = col.
// ---------------------------------------------------------------------------
__global__ __launch_bounds__(256) void kA() {
    const int r = blockIdx.x, b = blockIdx.y, c = threadIdx.x;
    float s = 0.f;
    for (int ch = 0; ch < NCH; ch++)
        s += g_Gp[((size_t)(b * NCH + ch) * CC + r) * CC + c];
    g_G[((size_t)b * CC + r) * CC + c] = s;
    if (r == 0) {
        float t = 0.f;
        for (int ch = 0; ch < NCH; ch++)
            t += g_sup[(size_t)(b * NCH + ch) * CC + c];
        g_su[(size_t)b * CC + c] = t;
    }
}

// ---------------------------------------------------------------------------
// kB1: P[leg][b,h] = W_h @ G   ([64x256] = [64x256] @ [256x256])
// grid (32 bh, 2 legs), 256 threads (8x32), 8x8 reg tile.
// ---------------------------------------------------------------------------
__global__ __launch_bounds__(256) void kB1(const float* __restrict__ Wk,
                                           const float* __restrict__ Wv) {
    __shared__ float As[8][68];
    __shared__ float Bs[8][264];
    const int bh = blockIdx.x, leg = blockIdx.y;
    const int b = bh >> 3, h = bh & 7;
    const float* W = (leg ? Wv : Wk) + (size_t)h * DD * CC;
    const float* Gb = g_G + (size_t)b * CC * CC;
    const int tid = threadIdx.x;
    const int tx = tid & 31, ty = tid >> 5;

    const int ad  = tid >> 1;          // 0..127 (valid if <64... tid<128)
    const int ak  = (tid & 1) * 4;
    const int br0 = tid >> 6,        bc0 = (tid & 63) * 4;
    const int br1 = (tid + 256) >> 6;

    float acc[8][8];
    #pragma unroll
    for (int i = 0; i < 8; i++) {
        #pragma unroll
        for (int j = 0; j < 8; j++) acc[i][j] = 0.f;
    }

    for (int kt = 0; kt < CC; kt += 8) {
        if (tid < 128) {
            float4 w = *(const float4*)(W + (size_t)ad * CC + kt + ak);
            As[ak+0][ad] = w.x; As[ak+1][ad] = w.y;
            As[ak+2][ad] = w.z; As[ak+3][ad] = w.w;
        }
        float4 g0 = *(const float4*)(Gb + (size_t)(kt + br0) * CC + bc0);
        float4 g1 = *(const float4*)(Gb + (size_t)(kt + br1) * CC + bc0);
        *(float4*)&Bs[br0][bc0] = g0;
        *(float4*)&Bs[br1][bc0] = g1;
        __syncthreads();
        #pragma unroll
        for (int kk = 0; kk < 8; kk++) {
            float a8[8], b8[8];
            *(float4*)&a8[0] = *(const float4*)&As[kk][ty*8];
            *(float4*)&a8[4] = *(const float4*)&As[kk][ty*8 + 4];
            *(float4*)&b8[0] = *(const float4*)&Bs[kk][tx*8];
            *(float4*)&b8[4] = *(const float4*)&Bs[kk][tx*8 + 4];
            #pragma unroll
            for (int i = 0; i < 8; i++) {
                #pragma unroll
                for (int j = 0; j < 8; j++)
                    acc[i][j] = fmaf(a8[i], b8[j], acc[i][j]);
            }
        }
        __syncthreads();
    }

    float* op = g_P + (size_t)(leg * BB * HH + bh) * DD * CC;
    #pragma unroll
    for (int i = 0; i < 8; i++) {
        float* orow = op + (size_t)(ty*8 + i) * CC + tx*8;
        #pragma unroll
        for (int j = 0; j < 8; j++) orow[j] = acc[i][j];
    }
}

// ---------------------------------------------------------------------------
// kB2: per (b,h): kv_raw = Pk @ Wv_h^T; stats from Pk/Pv diag dots + su;
// normalize -> g_kvhat. grid 32, 256 threads (16x16), 4x4 reg tile, K=256.
// ---------------------------------------------------------------------------
__global__ __launch_bounds__(256) void kB2(const float* __restrict__ Wk,
                                           const float* __restrict__ Wv) {
    __shared__ float As[8][68];
    __shared__ float Bs[8][68];
    __shared__ __align__(16) float sus[CC];
    __shared__ float mk[DD], rk[DD], mv[DD], rv[DD];
    const int bh = blockIdx.x;
    const int b = bh >> 3, h = bh & 7;
    const int tid = threadIdx.x;
    const int tx = tid & 15, ty = tid >> 4;
    const float invN = 1.f / NN;

    const float* Pk  = g_P + (size_t)bh * DD * CC;
    const float* Pv  = g_P + (size_t)(BB * HH + bh) * DD * CC;
    const float* WkH = Wk + (size_t)h * DD * CC;
    const float* WvH = Wv + (size_t)h * DD * CC;

    sus[tid] = g_su[(size_t)b * CC + tid];

    float acc[4][4];
    #pragma unroll
    for (int i = 0; i < 4; i++) {
        #pragma unroll
        for (int j = 0; j < 4; j++) acc[i][j] = 0.f;
    }

    for (int kt = 0; kt < CC; kt += 8) {
        if (tid < 128) {
            const int d = tid >> 1, kk0 = (tid & 1) * 4;
            float4 p = *(const float4*)(Pk + (size_t)d * CC + kt + kk0);
            As[kk0+0][d] = p.x; As[kk0+1][d] = p.y;
            As[kk0+2][d] = p.z; As[kk0+3][d] = p.w;
        } else {
            const int e = (tid - 128) >> 1, kk0 = (tid & 1) * 4;
            float4 w = *(const float4*)(WvH + (size_t)e * CC + kt + kk0);
            Bs[kk0+0][e] = w.x; Bs[kk0+1][e] = w.y;
            Bs[kk0+2][e] = w.z; Bs[kk0+3][e] = w.w;
        }
        __syncthreads();
        #pragma unroll
        for (int kk = 0; kk < 8; kk++) {
            float4 a4 = *(const float4*)&As[kk][ty*4];
            float4 b4 = *(const float4*)&Bs[kk][tx*4];
            float aa[4] = {a4.x, a4.y, a4.z, a4.w};
            float bb[4] = {b4.x, b4.y, b4.z, b4.w};
            #pragma unroll
            for (int i = 0; i < 4; i++) {
                #pragma unroll
                for (int j = 0; j < 4; j++)
                    acc[i][j] = fmaf(aa[i], bb[j], acc[i][j]);
            }
        }
        __syncthreads();
    }

    // stats: threads 0..63 -> k leg, 64..127 -> v leg
    if (tid < 128) {
        const int d = tid & 63;
        const float* P = (tid < 64) ? Pk : Pv;
        const float* W = (tid < 64) ? WkH : WvH;
        float ss = 0.f, sm = 0.f;
        for (int c = 0; c < CC; c += 4) {
            float4 p = *(const float4*)(P + (size_t)d * CC + c);
            float4 w = *(const float4*)(W + (size_t)d * CC + c);
            float4 s4 = *(const float4*)&sus[c];
            ss = fmaf(p.x, w.x, ss); ss = fmaf(p.y, w.y, ss);
            ss = fmaf(p.z, w.z, ss); ss = fmaf(p.w, w.w, ss);
            sm = fmaf(w.x, s4.x, sm); sm = fmaf(w.y, s4.y, sm);
            sm = fmaf(w.z, s4.z, sm); sm = fmaf(w.w, s4.w, sm);
        }
        const float m = sm * invN;
        const float r = rsqrtf(ss * invN - m * m + 1e-5f);
        if (tid < 64) { mk[d] = m; rk[d] = r; }
        else          { mv[d] = m; rv[d] = r; }
    }
    __syncthreads();

    float* op = g_kvhat + (size_t)bh * DD * DD;
    #pragma unroll
    for (int i = 0; i < 4; i++) {
        const int d = ty*4 + i;
        #pragma unroll
        for (int j = 0; j < 4; j++) {
            const int e = tx*4 + j;
            op[d * DD + e] = rk[d] * rv[e] * (acc[i][j] * invN - mk[d] * mv[e]);
        }
    }
}

// ---------------------------------------------------------------------------
// k3_T: T[b][c][h*64+e] = sum_d Wq[h*64+d][c] * kvhat[d][e]
// grid 32 (bh), 256 threads (thread = channel c).
// ---------------------------------------------------------------------------
__global__ __launch_bounds__(256) void k3_T(const float* __restrict__ Wq) {
    __shared__ float kvs[DD][DD];
    const int bh = blockIdx.x;
    const int b = bh >> 3, h = bh & 7;
    const int tid = threadIdx.x;

    for (int idx = tid; idx < DD * DD; idx += 256)
        kvs[idx >> 6][idx & 63] = g_kvhat[(size_t)bh * DD * DD + idx];
    __syncthreads();

    float accT[64];
    #pragma unroll
    for (int e = 0; e < 64; e++) accT[e] = 0.f;
    const int c = tid;
    for (int d = 0; d < DD; d++) {
        const float wq = Wq[(size_t)(h * DD + d) * CC + c];
        #pragma unroll
        for (int e4 = 0; e4 < 16; e4++) {
            float4 t = *(const float4*)&kvs[d][e4 * 4];
            accT[e4*4+0] = fmaf(wq, t.x, accT[e4*4+0]);
            accT[e4*4+1] = fmaf(wq, t.y, accT[e4*4+1]);
            accT[e4*4+2] = fmaf(wq, t.z, accT[e4*4+2]);
            accT[e4*4+3] = fmaf(wq, t.w, accT[e4*4+3]);
        }
    }
    float* Tp = g_T + ((size_t)b * CC + c) * HD + h * DD;
    #pragma unroll
    for (int e = 0; e < 64; e++) Tp[e] = accT[e];
}

// ---------------------------------------------------------------------------
// k3c_F: F[b] (256x256) = T[b] (256x512) @ Wo^T (Wo is [256,512] row-major).
// ---------------------------------------------------------------------------
__global__ __launch_bounds__(256) void k3c_F(const float* __restrict__ Wo) {
    __shared__ float Ts[16][32];
    __shared__ float Wos[16][34];
    const int o0 = blockIdx.x * 16;
    const int c0 = blockIdx.y * 16;
    const int b  = blockIdx.z;
    const int tid = threadIdx.x;
    const int tx = tid & 15, ty = tid >> 4;
    const int lr  = tid >> 4;
    const int lc2 = (tid & 15) * 2;
    float acc = 0.f;
    for (int j0 = 0; j0 < HD; j0 += 32) {
        float2 t = *(const float2*)&g_T[((size_t)b * CC + c0 + lr) * HD + j0 + lc2];
        Ts[lr][lc2] = t.x; Ts[lr][lc2 + 1] = t.y;
        float2 w = *(const float2*)&Wo[(size_t)(o0 + lr) * HD + j0 + lc2];
        Wos[lr][lc2] = w.x; Wos[lr][lc2 + 1] = w.y;
        __syncthreads();
        #pragma unroll
        for (int j = 0; j < 32; j++) acc = fmaf(Ts[ty][j], Wos[tx][j], acc);
        __syncthreads();
    }
    g_F[((size_t)b * CC + c0 + ty) * OUTC + o0 + tx] = acc;
}

// ---------------------------------------------------------------------------
// k4: out[token][o] = sum_c U[token][c] * F[b][c][o] + bo[o]
// ---------------------------------------------------------------------------
__global__ __launch_bounds__(256) void k4_out(const float* __restrict__ U,
                                              const float* __restrict__ bo,
                                              float* __restrict__ out) {
    __shared__ float As[8][132];
    __shared__ float Bs[8][132];
    const int ot0 = blockIdx.x * 128;
    const int mt0 = blockIdx.y * 128;
    const int b = mt0 >> 14;
    const float* Fp = g_F + (size_t)b * CC * OUTC;
    const int tid = threadIdx.x;
    const int tx = tid & 15, ty = tid >> 4;
    const int lrow = tid >> 1;
    const int lk4  = (tid & 1) * 4;
    const int brow = tid >> 5;
    const int bc4  = (tid & 31) * 4;

    float acc[8][8];
    #pragma unroll
    for (int i = 0; i < 8; i++) {
        #pragma unroll
        for (int j = 0; j < 8; j++) acc[i][j] = 0.f;
    }

    const float* Arow = U + (size_t)(mt0 + lrow) * CC + lk4;

    for (int kt = 0; kt < CC; kt += 8) {
        float4 a = *(const float4*)(Arow + kt);
        As[lk4+0][lrow] = a.x; As[lk4+1][lrow] = a.y;
        As[lk4+2][lrow] = a.z; As[lk4+3][lrow] = a.w;
        float4 f = *(const float4*)&Fp[(size_t)(kt + brow) * OUTC + ot0 + bc4];
        *(float4*)&Bs[brow][bc4] = f;
        __syncthreads();
        #pragma unroll
        for (int k = 0; k < 8; ++k) {
            float a8[8], b8[8];
            *(float4*)&a8[0] = *(const float4*)&As[k][ty*8];
            *(float4*)&a8[4] = *(const float4*)&As[k][ty*8+4];
            *(float4*)&b8[0] = *(const float4*)&Bs[k][tx*8];
            *(float4*)&b8[4] = *(const float4*)&Bs[k][tx*8+4];
            #pragma unroll
            for (int i = 0; i < 8; i++) {
                #pragma unroll
                for (int j = 0; j < 8; j++)
                    acc[i][j] = fmaf(a8[i], b8[j], acc[i][j]);
            }
        }
        __syncthreads();
    }

    float bias[8];
    #pragma unroll
    for (int j = 0; j < 8; j++) bias[j] = bo[ot0 + tx*8 + j];
    #pragma unroll
    for (int i = 0; i < 8; i++) {
        const int token = mt0 + ty * 8 + i;
        float* orow = out + (size_t)token * OUTC + ot0 + tx * 8;
        #pragma unroll
        for (int j = 0; j < 8; j++) orow[j] = acc[i][j] + bias[j];
    }
}

// ---------------------------------------------------------------------------
extern "C" void kernel_launch(void* const* d_in, const int* in_sizes, int n_in,
                              void* d_out, int out_size) {
    const float* u  = (const float*)d_in[0];
    // d_in[1] = pos_src -- unused by the reference computation
    const float* Wq = (const float*)d_in[2];
    const float* Wk = (const float*)d_in[3];
    const float* Wv = (const float*)d_in[4];
    const float* Wo = (const float*)d_in[5];
    const float* bo = (const float*)d_in[6];
    float* out = (float*)d_out;

    k_g  <<<dim3(4, NCH, BB), 256>>>(u);
    kA   <<<dim3(CC, BB), 256>>>();
    kB1  <<<dim3(BB * HH, 2), 256>>>(Wk, Wv);
    kB2  <<<BB * HH, 256>>>(Wk, Wv);
    k3_T <<<BB * HH, 256>>>(Wq);
    k3c_F<<<dim3(16, 16, BB), 256>>>(Wo);
    k4_out<<<dim3(2, 512), 256>>>(u, bo, out);
}

// round 5
// speedup vs baseline: 4.0184x; 1.3496x over previous
#include <cuda_runtime.h>
#include <cstdint>

#define BB 4
#define NN 16384
#define CC 256
#define HH 8
#define DD 64
#define HD 512
#define OUTC 256
#define NCH 32           // split-K chunks over the grid axis for G
#define KCH 512          // tokens per chunk

// static device scratch
__device__ float g_Gp[BB*NCH*CC*CC];     // per-chunk partials of G = U^T U (3 tiles used)
__device__ float g_sup[BB*NCH*CC];       // per-chunk column sums of U
__device__ float g_G[BB*CC*CC];          // reduced Gram matrices
__device__ float g_su[BB*CC];            // reduced column sums
__device__ float g_P[2*BB*HH*DD*CC];     // P[leg][bh] = W_h @ G   (64 x 256)
__device__ float g_kvhat[BB*HH*DD*DD];   // normalized kv matrices
__device__ float g_T[BB*CC*HD];          // Wq_h^T @ kvhat, [b][c][h*64+e]
__device__ float g_F[BB*CC*OUTC];        // F per batch: [c][o]

__device__ __forceinline__ unsigned to_tf32(float v) {
    unsigned t;
    asm("cvt.rna.tf32.f32 %0, %1;" : "=r"(t) : "f"(v));
    return t;
}

// ---------------------------------------------------------------------------
// k_g: split-K syrk partials, symmetric (3 tiles of the 2x2).
// ---------------------------------------------------------------------------
__global__ __launch_bounds__(256) void k_g(const float* __restrict__ U) {
    __shared__ float Us[8][264];
    const int tile = blockIdx.x;            // 0..2 -> (0,0),(0,1),(1,1)
    const int ti = tile >> 1, tj = (tile + 1) >> 1;
    const int ch = blockIdx.y, b = blockIdx.z;
    const int tid = threadIdx.x;
    const int tx = tid & 15, ty = tid >> 4;

    const int row0 = tid >> 6,         c0 = (tid & 63) * 4;
    const int row1 = (tid + 256) >> 6, c1 = (tid & 63) * 4;

    const float* Up = U + (size_t)(b * NN + ch * KCH) * CC;

    float acc[8][8];
    #pragma unroll
    for (int i = 0; i < 8; i++) {
        #pragma unroll
        for (int j = 0; j < 8; j++) acc[i][j] = 0.f;
    }
    float s = 0.f;

    for (int t0 = 0; t0 < KCH; t0 += 8) {
        const float* Ut = Up + (size_t)t0 * CC;
        float4 a0 = *(const float4*)(Ut + (size_t)row0 * CC + c0);
        float4 a1 = *(const float4*)(Ut + (size_t)row1 * CC + c1);
        *(float4*)&Us[row0][c0] = a0;
        *(float4*)&Us[row1][c1] = a1;
        __syncthreads();
        #pragma unroll
        for (int kk = 0; kk < 8; kk++) {
            float a8[8], b8[8];
            *(float4*)&a8[0] = *(const float4*)&Us[kk][ti*128 + ty*8];
            *(float4*)&a8[4] = *(const float4*)&Us[kk][ti*128 + ty*8 + 4];
            *(float4*)&b8[0] = *(const float4*)&Us[kk][tj*128 + tx*8];
            *(float4*)&b8[4] = *(const float4*)&Us[kk][tj*128 + tx*8 + 4];
            #pragma unroll
            for (int i = 0; i < 8; i++) {
                #pragma unroll
                for (int j = 0; j < 8; j++)
                    acc[i][j] = fmaf(a8[i], b8[j], acc[i][j]);
            }
        }
        if (tile == 0) {
            #pragma unroll
            for (int kk = 0; kk < 8; kk++) s += Us[kk][tid];
        }
        __syncthreads();
    }

    float* op = g_Gp + (size_t)(b * NCH + ch) * CC * CC;
    #pragma unroll
    for (int i = 0; i < 8; i++) {
        float* orow = op + (size_t)(ti*128 + ty*8 + i) * CC + tj*128 + tx*8;
        #pragma unroll
        for (int j = 0; j < 8; j++) orow[j] = acc[i][j];
    }
    if (tile == 0) g_sup[(size_t)(b * NCH + ch) * CC + tid] = s;
}

// ---------------------------------------------------------------------------
// kA: reduce split-K partials for stored tiles -> g_G, g_su.
// ---------------------------------------------------------------------------
__global__ __launch_bounds__(256) void kA() {
    const int r = blockIdx.x, b = blockIdx.y, c = threadIdx.x;
    if (r < 128 || c >= 128) {
        float s = 0.f;
        for (int ch = 0; ch < NCH; ch++)
            s += g_Gp[((size_t)(b * NCH + ch) * CC + r) * CC + c];
        g_G[((size_t)b * CC + r) * CC + c] = s;
    }
    if (r == 0) {
        float t = 0.f;
        for (int ch = 0; ch < NCH; ch++)
            t += g_sup[(size_t)(b * NCH + ch) * CC + c];
        g_su[(size_t)b * CC + c] = t;
    }
}

// kA2: mirror the lower-left quadrant of G by symmetry.
__global__ __launch_bounds__(128) void kA2() {
    const int r = 128 + blockIdx.x, b = blockIdx.y, c = threadIdx.x;  // c in 0..127
    g_G[((size_t)b * CC + r) * CC + c] = g_G[((size_t)b * CC + c) * CC + r];
}

// ---------------------------------------------------------------------------
// kB1: P[leg][b,h] = W_h @ G   ([64x256] = [64x256] @ [256x256])
// ---------------------------------------------------------------------------
__global__ __launch_bounds__(256) void kB1(const float* __restrict__ Wk,
                                           const float* __restrict__ Wv) {
    __shared__ float As[8][68];
    __shared__ float Bs[8][264];
    const int bh = blockIdx.x, leg = blockIdx.y;
    const int b = bh >> 3, h = bh & 7;
    const float* W = (leg ? Wv : Wk) + (size_t)h * DD * CC;
    const float* Gb = g_G + (size_t)b * CC * CC;
    const int tid = threadIdx.x;
    const int tx = tid & 31, ty = tid >> 5;

    const int ad  = tid >> 1;
    const int ak  = (tid & 1) * 4;
    const int br0 = tid >> 6,        bc0 = (tid & 63) * 4;
    const int br1 = (tid + 256) >> 6;

    float acc[8][8];
    #pragma unroll
    for (int i = 0; i < 8; i++) {
        #pragma unroll
        for (int j = 0; j < 8; j++) acc[i][j] = 0.f;
    }

    for (int kt = 0; kt < CC; kt += 8) {
        if (tid < 128) {
            float4 w = *(const float4*)(W + (size_t)ad * CC + kt + ak);
            As[ak+0][ad] = w.x; As[ak+1][ad] = w.y;
            As[ak+2][ad] = w.z; As[ak+3][ad] = w.w;
        }
        float4 g0 = *(const float4*)(Gb + (size_t)(kt + br0) * CC + bc0);
        float4 g1 = *(const float4*)(Gb + (size_t)(kt + br1) * CC + bc0);
        *(float4*)&Bs[br0][bc0] = g0;
        *(float4*)&Bs[br1][bc0] = g1;
        __syncthreads();
        #pragma unroll
        for (int kk = 0; kk < 8; kk++) {
            float a8[8], b8[8];
            *(float4*)&a8[0] = *(const float4*)&As[kk][ty*8];
            *(float4*)&a8[4] = *(const float4*)&As[kk][ty*8 + 4];
            *(float4*)&b8[0] = *(const float4*)&Bs[kk][tx*8];
            *(float4*)&b8[4] = *(const float4*)&Bs[kk][tx*8 + 4];
            #pragma unroll
            for (int i = 0; i < 8; i++) {
                #pragma unroll
                for (int j = 0; j < 8; j++)
                    acc[i][j] = fmaf(a8[i], b8[j], acc[i][j]);
            }
        }
        __syncthreads();
    }

    float* op = g_P + (size_t)(leg * BB * HH + bh) * DD * CC;
    #pragma unroll
    for (int i = 0; i < 8; i++) {
        float* orow = op + (size_t)(ty*8 + i) * CC + tx*8;
        #pragma unroll
        for (int j = 0; j < 8; j++) orow[j] = acc[i][j];
    }
}

// ---------------------------------------------------------------------------
// kB2: per (b,h): kv_raw = Pk @ Wv_h^T; stats; normalize -> g_kvhat.
// ---------------------------------------------------------------------------
__global__ __launch_bounds__(256) void kB2(const float* __restrict__ Wk,
                                           const float* __restrict__ Wv) {
    __shared__ float As[8][68];
    __shared__ float Bs[8][68];
    __shared__ __align__(16) float sus[CC];
    __shared__ float mk[DD], rk[DD], mv[DD], rv[DD];
    const int bh = blockIdx.x;
    const int b = bh >> 3, h = bh & 7;
    const int tid = threadIdx.x;
    const int tx = tid & 15, ty = tid >> 4;
    const float invN = 1.f / NN;

    const float* Pk  = g_P + (size_t)bh * DD * CC;
    const float* Pv  = g_P + (size_t)(BB * HH + bh) * DD * CC;
    const float* WkH = Wk + (size_t)h * DD * CC;
    const float* WvH = Wv + (size_t)h * DD * CC;

    sus[tid] = g_su[(size_t)b * CC + tid];

    float acc[4][4];
    #pragma unroll
    for (int i = 0; i < 4; i++) {
        #pragma unroll
        for (int j = 0; j < 4; j++) acc[i][j] = 0.f;
    }

    for (int kt = 0; kt < CC; kt += 8) {
        if (tid < 128) {
            const int d = tid >> 1, kk0 = (tid & 1) * 4;
            float4 p = *(const float4*)(Pk + (size_t)d * CC + kt + kk0);
            As[kk0+0][d] = p.x; As[kk0+1][d] = p.y;
            As[kk0+2][d] = p.z; As[kk0+3][d] = p.w;
        } else {
            const int e = (tid - 128) >> 1, kk0 = (tid & 1) * 4;
            float4 w = *(const float4*)(WvH + (size_t)e * CC + kt + kk0);
            Bs[kk0+0][e] = w.x; Bs[kk0+1][e] = w.y;
            Bs[kk0+2][e] = w.z; Bs[kk0+3][e] = w.w;
        }
        __syncthreads();
        #pragma unroll
        for (int kk = 0; kk < 8; kk++) {
            float4 a4 = *(const float4*)&As[kk][ty*4];
            float4 b4 = *(const float4*)&Bs[kk][tx*4];
            float aa[4] = {a4.x, a4.y, a4.z, a4.w};
            float bb[4] = {b4.x, b4.y, b4.z, b4.w};
            #pragma unroll
            for (int i = 0; i < 4; i++) {
                #pragma unroll
                for (int j = 0; j < 4; j++)
                    acc[i][j] = fmaf(aa[i], bb[j], acc[i][j]);
            }
        }
        __syncthreads();
    }

    if (tid < 128) {
        const int d = tid & 63;
        const float* P = (tid < 64) ? Pk : Pv;
        const float* W = (tid < 64) ? WkH : WvH;
        float ss = 0.f, sm = 0.f;
        for (int c = 0; c < CC; c += 4) {
            float4 p = *(const float4*)(P + (size_t)d * CC + c);
            float4 w = *(const float4*)(W + (size_t)d * CC + c);
            float4 s4 = *(const float4*)&sus[c];
            ss = fmaf(p.x, w.x, ss); ss = fmaf(p.y, w.y, ss);
            ss = fmaf(p.z, w.z, ss); ss = fmaf(p.w, w.w, ss);
            sm = fmaf(w.x, s4.x, sm); sm = fmaf(w.y, s4.y, sm);
            sm = fmaf(w.z, s4.z, sm); sm = fmaf(w.w, s4.w, sm);
        }
        const float m = sm * invN;
        const float r = rsqrtf(ss * invN - m * m + 1e-5f);
        if (tid < 64) { mk[d] = m; rk[d] = r; }
        else          { mv[d] = m; rv[d] = r; }
    }
    __syncthreads();

    float* op = g_kvhat + (size_t)bh * DD * DD;
    #pragma unroll
    for (int i = 0; i < 4; i++) {
        const int d = ty*4 + i;
        #pragma unroll
        for (int j = 0; j < 4; j++) {
            const int e = tx*4 + j;
            op[d * DD + e] = rk[d] * rv[e] * (acc[i][j] * invN - mk[d] * mv[e]);
        }
    }
}

// ---------------------------------------------------------------------------
// k3_T: T[b][c][h*64+e] = sum_d Wq[h*64+d][c] * kvhat[d][e]
// ---------------------------------------------------------------------------
__global__ __launch_bounds__(256) void k3_T(const float* __restrict__ Wq) {
    __shared__ float kvs[DD][DD];
    const int bh = blockIdx.x;
    const int b = bh >> 3, h = bh & 7;
    const int tid = threadIdx.x;

    for (int idx = tid; idx < DD * DD; idx += 256)
        kvs[idx >> 6][idx & 63] = g_kvhat[(size_t)bh * DD * DD + idx];
    __syncthreads();

    float accT[64];
    #pragma unroll
    for (int e = 0; e < 64; e++) accT[e] = 0.f;
    const int c = tid;
    for (int d = 0; d < DD; d++) {
        const float wq = Wq[(size_t)(h * DD + d) * CC + c];
        #pragma unroll
        for (int e4 = 0; e4 < 16; e4++) {
            float4 t = *(const float4*)&kvs[d][e4 * 4];
            accT[e4*4+0] = fmaf(wq, t.x, accT[e4*4+0]);
            accT[e4*4+1] = fmaf(wq, t.y, accT[e4*4+1]);
            accT[e4*4+2] = fmaf(wq, t.z, accT[e4*4+2]);
            accT[e4*4+3] = fmaf(wq, t.w, accT[e4*4+3]);
        }
    }
    float* Tp = g_T + ((size_t)b * CC + c) * HD + h * DD;
    #pragma unroll
    for (int e = 0; e < 64; e++) Tp[e] = accT[e];
}

// ---------------------------------------------------------------------------
// k3c_F: F[b] (256x256, [c][o]) = T[b] (256x512) @ Wo^T.
// ---------------------------------------------------------------------------
__global__ __launch_bounds__(256) void k3c_F(const float* __restrict__ Wo) {
    __shared__ float Ts[16][32];
    __shared__ float Wos[16][34];
    const int o0 = blockIdx.x * 16;
    const int c0 = blockIdx.y * 16;
    const int b  = blockIdx.z;
    const int tid = threadIdx.x;
    const int tx = tid & 15, ty = tid >> 4;
    const int lr  = tid >> 4;
    const int lc2 = (tid & 15) * 2;
    float acc = 0.f;
    for (int j0 = 0; j0 < HD; j0 += 32) {
        float2 t = *(const float2*)&g_T[((size_t)b * CC + c0 + lr) * HD + j0 + lc2];
        Ts[lr][lc2] = t.x; Ts[lr][lc2 + 1] = t.y;
        float2 w = *(const float2*)&Wo[(size_t)(o0 + lr) * HD + j0 + lc2];
        Wos[lr][lc2] = w.x; Wos[lr][lc2 + 1] = w.y;
        __syncthreads();
        #pragma unroll
        for (int j = 0; j < 32; j++) acc = fmaf(Ts[ty][j], Wos[tx][j], acc);
        __syncthreads();
    }
    g_F[((size_t)b * CC + c0 + ty) * OUTC + o0 + tx] = acc;
}

// ---------------------------------------------------------------------------
// k4_mma: out = U @ F + bo using mma.sync tf32 (standard sm_80+ PTX).
// CTA: 256 threads = 8 warps (4 m x 2 n), CTA tile 128x128, K = 256 in
// chunks of 32. Warp tile 32x64 (2 x 8 mma tiles of m16n8k8).
// As[k][m] / Bs[k][n], rows padded to 132 floats -> conflict-free frag loads.
// ---------------------------------------------------------------------------
__global__ __launch_bounds__(256) void k4_mma(const float* __restrict__ U,
                                              const float* __restrict__ bo,
                                              float* __restrict__ out) {
    __shared__ unsigned As[32][132];
    __shared__ unsigned Bs[32][132];

    const int tid = threadIdx.x;
    const int wid = tid >> 5, lane = tid & 31;
    const int warp_m = wid & 3;          // 0..3  (32 rows each)
    const int warp_n = wid >> 2;         // 0..1  (64 cols each)
    const int gr = lane >> 2;            // 0..7
    const int tc = lane & 3;             // 0..3

    const int n0  = blockIdx.x * 128;
    const int mt0 = blockIdx.y * 128;
    const int b   = mt0 >> 14;
    const float* Fp = g_F + (size_t)b * CC * OUTC;

    float acc[2][8][4];
    #pragma unroll
    for (int mi = 0; mi < 2; mi++)
        #pragma unroll
        for (int ni = 0; ni < 8; ni++)
            #pragma unroll
            for (int q = 0; q < 4; q++) acc[mi][ni][q] = 0.f;

    const int am  = tid >> 3;            // 0..31 (plus p*32)
    const int akq = (tid & 7) * 4;       // 0..28
    const int bk  = tid >> 5;            // 0..7 (plus p*8)
    const int bnq = (tid & 31) * 4;      // 0..124

    for (int c = 0; c < 8; c++) {
        const int k0 = c * 32;
        // load A chunk: U[mt0+m][k0+k] -> As[k][m] (transposed, tf32)
        #pragma unroll
        for (int p = 0; p < 4; p++) {
            const int m = am + p * 32;
            float4 v = *(const float4*)(U + (size_t)(mt0 + m) * CC + k0 + akq);
            As[akq + 0][m] = to_tf32(v.x);
            As[akq + 1][m] = to_tf32(v.y);
            As[akq + 2][m] = to_tf32(v.z);
            As[akq + 3][m] = to_tf32(v.w);
        }
        // load B chunk: F[k0+k][n0+n] -> Bs[k][n] (tf32)
        #pragma unroll
        for (int p = 0; p < 4; p++) {
            const int k = bk + p * 8;
            float4 v = *(const float4*)(Fp + (size_t)(k0 + k) * OUTC + n0 + bnq);
            uint4 t;
            t.x = to_tf32(v.x); t.y = to_tf32(v.y);
            t.z = to_tf32(v.z); t.w = to_tf32(v.w);
            *(uint4*)&Bs[k][bnq] = t;
        }
        __syncthreads();

        #pragma unroll
        for (int ks = 0; ks < 4; ks++) {
            const int k8 = ks * 8;
            unsigned a[2][4];
            #pragma unroll
            for (int mi = 0; mi < 2; mi++) {
                const int mr = warp_m * 32 + mi * 16;
                a[mi][0] = As[k8 + tc][mr + gr];
                a[mi][1] = As[k8 + tc][mr + gr + 8];
                a[mi][2] = As[k8 + tc + 4][mr + gr];
                a[mi][3] = As[k8 + tc + 4][mr + gr + 8];
            }
            #pragma unroll
            for (int ni = 0; ni < 8; ni++) {
                const int nb = warp_n * 64 + ni * 8;
                unsigned b0 = Bs[k8 + tc][nb + gr];
                unsigned b1 = Bs[k8 + tc + 4][nb + gr];
                #pragma unroll
                for (int mi = 0; mi < 2; mi++) {
                    asm volatile(
                        "mma.sync.aligned.m16n8k8.row.col.f32.tf32.tf32.f32 "
                        "{%0,%1,%2,%3}, {%4,%5,%6,%7}, {%8,%9}, {%0,%1,%2,%3};"
                        : "+f"(acc[mi][ni][0]), "+f"(acc[mi][ni][1]),
                          "+f"(acc[mi][ni][2]), "+f"(acc[mi][ni][3])
                        : "r"(a[mi][0]), "r"(a[mi][1]), "r"(a[mi][2]), "r"(a[mi][3]),
                          "r"(b0), "r"(b1));
                }
            }
        }
        __syncthreads();
    }

    // epilogue: add bias, store
    #pragma unroll
    for (int mi = 0; mi < 2; mi++) {
        const int row = mt0 + warp_m * 32 + mi * 16 + gr;
        #pragma unroll
        for (int ni = 0; ni < 8; ni++) {
            const int col = n0 + warp_n * 64 + ni * 8 + tc * 2;
            const float2 bb = *(const float2*)(bo + col);
            float2 o0, o1;
            o0.x = acc[mi][ni][0] + bb.x;
            o0.y = acc[mi][ni][1] + bb.y;
            o1.x = acc[mi][ni][2] + bb.x;
            o1.y = acc[mi][ni][3] + bb.y;
            *(float2*)(out + (size_t)row * OUTC + col) = o0;
            *(float2*)(out + (size_t)(row + 8) * OUTC + col) = o1;
        }
    }
}

// ---------------------------------------------------------------------------
extern "C" void kernel_launch(void* const* d_in, const int* in_sizes, int n_in,
                              void* d_out, int out_size) {
    const float* u  = (const float*)d_in[0];
    // d_in[1] = pos_src -- unused by the reference computation
    const float* Wq = (const float*)d_in[2];
    const float* Wk = (const float*)d_in[3];
    const float* Wv = (const float*)d_in[4];
    const float* Wo = (const float*)d_in[5];
    const float* bo = (const float*)d_in[6];
    float* out = (float*)d_out;

    k_g  <<<dim3(3, NCH, BB), 256>>>(u);
    kA   <<<dim3(CC, BB), 256>>>();
    kA2  <<<dim3(128, BB), 128>>>();
    kB1  <<<dim3(BB * HH, 2), 256>>>(Wk, Wv);
    kB2  <<<BB * HH, 256>>>(Wk, Wv);
    k3_T <<<BB * HH, 256>>>(Wq);
    k3c_F<<<dim3(16, 16, BB), 256>>>(Wo);
    k4_mma<<<dim3(2, 512), 256>>>(u, bo, out);
}

// round 6
// speedup vs baseline: 5.1240x; 1.2751x over previous
#include <cuda_runtime.h>
#include <cstdint>

#define BB 4
#define NN 16384
#define CC 256
#define HH 8
#define DD 64
#define HD 512
#define OUTC 256
#define NCH 32           // split-K chunks over the grid axis for G
#define KCH 512          // tokens per chunk

// static device scratch
__device__ float g_Gp[BB*NCH*CC*CC];     // per-chunk partials of G = U^T U
__device__ float g_sup[BB*NCH*CC];       // per-chunk column sums of U
__device__ float g_G[BB*CC*CC];          // reduced Gram matrices
__device__ float g_su[BB*CC];            // reduced column sums
__device__ float g_P[2*BB*HH*DD*CC];     // P[leg][bh] = W_h @ G   (64 x 256)
__device__ float g_kvhat[BB*HH*DD*DD];   // normalized kv matrices
__device__ float g_T[BB*CC*HD];          // Wq_h^T @ kvhat, [b][c][h*64+e]
__device__ float g_F[BB*CC*OUTC];        // F per batch: [c][o]

__device__ __forceinline__ unsigned to_tf32(float v) {
    unsigned t;
    asm("cvt.rna.tf32.f32 %0, %1;" : "=r"(t) : "f"(v));
    return t;
}

#define MMA8(accp, a0, a1, a2, a3, b0, b1) \
    asm volatile( \
        "mma.sync.aligned.m16n8k8.row.col.f32.tf32.tf32.f32 " \
        "{%0,%1,%2,%3}, {%4,%5,%6,%7}, {%8,%9}, {%0,%1,%2,%3};" \
        : "+f"((accp)[0]), "+f"((accp)[1]), "+f"((accp)[2]), "+f"((accp)[3]) \
        : "r"(a0), "r"(a1), "r"(a2), "r"(a3), "r"(b0), "r"(b1))

// ---------------------------------------------------------------------------
// k_g: split-K syrk partials via tf32x3 mma (fp32-accurate Gram).
// grid (3 tiles, NCH, BB); tile -> quadrant (0,0),(0,1),(1,1).
// Block: 256 thr, 8 warps scattered over the 128x128 output quadrant.
// Diagonal quadrants skip strictly-sub-diagonal 16x8 mma tiles.
// ---------------------------------------------------------------------------
__global__ __launch_bounds__(256) void k_g(const float* __restrict__ U) {
    __shared__ unsigned Hi[16][260];
    __shared__ unsigned Lo[16][260];
    const int tile = blockIdx.x;            // 0..2
    const int ti = tile >> 1, tj = (tile + 1) >> 1;
    const int ch = blockIdx.y, b = blockIdx.z;
    const int tid = threadIdx.x;
    const int wid = tid >> 5, lane = tid & 31;
    const int warp_m = wid & 3, warp_n = wid >> 2;
    const int gr = lane >> 2, tc = lane & 3;
    const bool diag = (ti == tj);

    const float* Up = U + (size_t)(b * NN + ch * KCH) * CC;

    float acc[2][8][4];
    #pragma unroll
    for (int mi = 0; mi < 2; mi++)
        #pragma unroll
        for (int ni = 0; ni < 8; ni++)
            #pragma unroll
            for (int q = 0; q < 4; q++) acc[mi][ni][q] = 0.f;
    float s = 0.f;

    const int lrow = tid >> 4;           // token row 0..15
    const int lc0  = (tid & 15) * 16;    // 16 channels per thread

    for (int t0 = 0; t0 < KCH; t0 += 16) {
        const float* Ut = Up + (size_t)(t0 + lrow) * CC + lc0;
        float4 v[4];
        #pragma unroll
        for (int q = 0; q < 4; q++) v[q] = *(const float4*)(Ut + q * 4);
        __syncthreads();
        #pragma unroll
        for (int q = 0; q < 4; q++) {
            uint4 h, l;
            h.x = to_tf32(v[q].x); l.x = to_tf32(v[q].x - __uint_as_float(h.x));
            h.y = to_tf32(v[q].y); l.y = to_tf32(v[q].y - __uint_as_float(h.y));
            h.z = to_tf32(v[q].z); l.z = to_tf32(v[q].z - __uint_as_float(h.z));
            h.w = to_tf32(v[q].w); l.w = to_tf32(v[q].w - __uint_as_float(h.w));
            *(uint4*)&Hi[lrow][lc0 + q * 4] = h;
            *(uint4*)&Lo[lrow][lc0 + q * 4] = l;
        }
        __syncthreads();

        if (tile == 0) {
            #pragma unroll
            for (int k = 0; k < 16; k++)
                s += __uint_as_float(Hi[k][tid]) + __uint_as_float(Lo[k][tid]);
        }

        #pragma unroll
        for (int ks = 0; ks < 2; ks++) {
            const int k8 = ks * 8;
            unsigned ah[2][4], al[2][4];
            #pragma unroll
            for (int mi = 0; mi < 2; mi++) {
                const int am = ti * 128 + warp_m * 16 + mi * 64;
                ah[mi][0] = Hi[k8 + tc][am + gr];
                ah[mi][1] = Hi[k8 + tc][am + gr + 8];
                ah[mi][2] = Hi[k8 + tc + 4][am + gr];
                ah[mi][3] = Hi[k8 + tc + 4][am + gr + 8];
                al[mi][0] = Lo[k8 + tc][am + gr];
                al[mi][1] = Lo[k8 + tc][am + gr + 8];
                al[mi][2] = Lo[k8 + tc + 4][am + gr];
                al[mi][3] = Lo[k8 + tc + 4][am + gr + 8];
            }
            #pragma unroll
            for (int ni = 0; ni < 8; ni++) {
                const int nb = warp_n * 8 + ni * 16;
                const int bn = tj * 128 + nb;
                unsigned bh0 = Hi[k8 + tc][bn + gr];
                unsigned bh1 = Hi[k8 + tc + 4][bn + gr];
                unsigned bl0 = Lo[k8 + tc][bn + gr];
                unsigned bl1 = Lo[k8 + tc + 4][bn + gr];
                #pragma unroll
                for (int mi = 0; mi < 2; mi++) {
                    const int mr = warp_m * 16 + mi * 64;
                    if (diag && (nb + 8 <= mr)) continue;
                    MMA8(acc[mi][ni], ah[mi][0], ah[mi][1], ah[mi][2], ah[mi][3], bh0, bh1);
                    MMA8(acc[mi][ni], ah[mi][0], ah[mi][1], ah[mi][2], ah[mi][3], bl0, bl1);
                    MMA8(acc[mi][ni], al[mi][0], al[mi][1], al[mi][2], al[mi][3], bh0, bh1);
                }
            }
        }
    }

    float* op = g_Gp + (size_t)(b * NCH + ch) * CC * CC;
    #pragma unroll
    for (int mi = 0; mi < 2; mi++) {
        const int mr = warp_m * 16 + mi * 64;
        #pragma unroll
        for (int ni = 0; ni < 8; ni++) {
            const int nb = warp_n * 8 + ni * 16;
            if (diag && (nb + 8 <= mr)) continue;
            const int row = ti * 128 + mr + gr;
            const int col = tj * 128 + nb + tc * 2;
            float2 c0 = make_float2(acc[mi][ni][0], acc[mi][ni][1]);
            float2 c1 = make_float2(acc[mi][ni][2], acc[mi][ni][3]);
            *(float2*)(op + (size_t)row * CC + col) = c0;
            *(float2*)(op + (size_t)(row + 8) * CC + col) = c1;
        }
    }
    if (tile == 0) g_sup[(size_t)(b * NCH + ch) * CC + tid] = s;
}

// ---------------------------------------------------------------------------
// kA: reduce split-K partials -> g_G, g_su. Same-quadrant sub-diagonal
// elements are read from the transposed (computed) position.
// ---------------------------------------------------------------------------
__global__ __launch_bounds__(256) void kA() {
    const int r = blockIdx.x, b = blockIdx.y, c = threadIdx.x;
    if (r < 128 || c >= 128) {
        int rr = r, cc = c;
        if (((r >= 128) == (c >= 128)) && (c < r)) { rr = c; cc = r; }
        float s = 0.f;
        for (int ch = 0; ch < NCH; ch++)
            s += g_Gp[((size_t)(b * NCH + ch) * CC + rr) * CC + cc];
        g_G[((size_t)b * CC + r) * CC + c] = s;
    }
    if (r == 0) {
        float t = 0.f;
        for (int ch = 0; ch < NCH; ch++)
            t += g_sup[(size_t)(b * NCH + ch) * CC + c];
        g_su[(size_t)b * CC + c] = t;
    }
}

// kA2: mirror the lower-left quadrant of G by symmetry.
__global__ __launch_bounds__(128) void kA2() {
    const int r = 128 + blockIdx.x, b = blockIdx.y, c = threadIdx.x;  // c in 0..127
    g_G[((size_t)b * CC + r) * CC + c] = g_G[((size_t)b * CC + c) * CC + r];
}

// ---------------------------------------------------------------------------
// kB1: P[leg][b,h] = W_h @ G. grid (32 bh, 2 legs, 4 otiles) = 256 blocks.
// Block: 64x64 output, K=256 in steps of 16, register-prefetched.
// ---------------------------------------------------------------------------
__global__ __launch_bounds__(256) void kB1(const float* __restrict__ Wk,
                                           const float* __restrict__ Wv) {
    __shared__ float As[16][68];
    __shared__ float Bs[16][68];
    const int bh = blockIdx.x, leg = blockIdx.y, ot = blockIdx.z;
    const int b = bh >> 3, h = bh & 7;
    const float* W  = (leg ? Wv : Wk) + (size_t)h * DD * CC;
    const float* Gb = g_G + (size_t)b * CC * CC;
    const int o0 = ot * 64;
    const int tid = threadIdx.x;
    const int tx = tid & 15, ty = tid >> 4;

    const int ad = tid >> 2, akq = (tid & 3) * 4;   // A: row d, k-quad
    const int bk = tid >> 4, bc4 = (tid & 15) * 4;  // B: k row, col quad

    float acc[4][4];
    #pragma unroll
    for (int i = 0; i < 4; i++)
        #pragma unroll
        for (int j = 0; j < 4; j++) acc[i][j] = 0.f;

    float4 wA = *(const float4*)(W + (size_t)ad * CC + akq);
    float4 wB = *(const float4*)(Gb + (size_t)bk * CC + o0 + bc4);

    for (int kt = 0; kt < CC; kt += 16) {
        As[akq + 0][ad] = wA.x; As[akq + 1][ad] = wA.y;
        As[akq + 2][ad] = wA.z; As[akq + 3][ad] = wA.w;
        *(float4*)&Bs[bk][bc4] = wB;
        __syncthreads();
        if (kt + 16 < CC) {
            wA = *(const float4*)(W + (size_t)ad * CC + kt + 16 + akq);
            wB = *(const float4*)(Gb + (size_t)(kt + 16 + bk) * CC + o0 + bc4);
        }
        #pragma unroll
        for (int k = 0; k < 16; k++) {
            float4 a4 = *(const float4*)&As[k][ty * 4];
            float4 b4 = *(const float4*)&Bs[k][tx * 4];
            float aa[4] = {a4.x, a4.y, a4.z, a4.w};
            float bb[4] = {b4.x, b4.y, b4.z, b4.w};
            #pragma unroll
            for (int i = 0; i < 4; i++)
                #pragma unroll
                for (int j = 0; j < 4; j++)
                    acc[i][j] = fmaf(aa[i], bb[j], acc[i][j]);
        }
        __syncthreads();
    }

    float* op = g_P + (size_t)(leg * BB * HH + bh) * DD * CC;
    #pragma unroll
    for (int i = 0; i < 4; i++)
        #pragma unroll
        for (int j = 0; j < 4; j++)
            op[(size_t)(ty * 4 + i) * CC + o0 + tx * 4 + j] = acc[i][j];
}

// ---------------------------------------------------------------------------
// kB2: per (b,h): kv_raw = Pk @ Wv_h^T; stats; normalize -> g_kvhat.
// K-step 16 with register prefetch; stats loops unrolled for MLP.
// ---------------------------------------------------------------------------
__global__ __launch_bounds__(256) void kB2(const float* __restrict__ Wk,
                                           const float* __restrict__ Wv) {
    __shared__ float As[16][68];
    __shared__ float Bs[16][68];
    __shared__ __align__(16) float sus[CC];
    __shared__ float mk[DD], rk[DD], mv[DD], rv[DD];
    const int bh = blockIdx.x;
    const int b = bh >> 3, h = bh & 7;
    const int tid = threadIdx.x;
    const int tx = tid & 15, ty = tid >> 4;
    const float invN = 1.f / NN;

    const float* Pk  = g_P + (size_t)bh * DD * CC;
    const float* Pv  = g_P + (size_t)(BB * HH + bh) * DD * CC;
    const float* WkH = Wk + (size_t)h * DD * CC;
    const float* WvH = Wv + (size_t)h * DD * CC;

    sus[tid] = g_su[(size_t)b * CC + tid];

    const int ad = tid >> 2, akq = (tid & 3) * 4;

    float acc[4][4];
    #pragma unroll
    for (int i = 0; i < 4; i++)
        #pragma unroll
        for (int j = 0; j < 4; j++) acc[i][j] = 0.f;

    float4 pA = *(const float4*)(Pk + (size_t)ad * CC + akq);
    float4 pB = *(const float4*)(WvH + (size_t)ad * CC + akq);

    for (int kt = 0; kt < CC; kt += 16) {
        As[akq + 0][ad] = pA.x; As[akq + 1][ad] = pA.y;
        As[akq + 2][ad] = pA.z; As[akq + 3][ad] = pA.w;
        Bs[akq + 0][ad] = pB.x; Bs[akq + 1][ad] = pB.y;
        Bs[akq + 2][ad] = pB.z; Bs[akq + 3][ad] = pB.w;
        __syncthreads();
        if (kt + 16 < CC) {
            pA = *(const float4*)(Pk + (size_t)ad * CC + kt + 16 + akq);
            pB = *(const float4*)(WvH + (size_t)ad * CC + kt + 16 + akq);
        }
        #pragma unroll
        for (int k = 0; k < 16; k++) {
            float4 a4 = *(const float4*)&As[k][ty * 4];
            float4 b4 = *(const float4*)&Bs[k][tx * 4];
            float aa[4] = {a4.x, a4.y, a4.z, a4.w};
            float bb[4] = {b4.x, b4.y, b4.z, b4.w};
            #pragma unroll
            for (int i = 0; i < 4; i++)
                #pragma unroll
                for (int j = 0; j < 4; j++)
                    acc[i][j] = fmaf(aa[i], bb[j], acc[i][j]);
        }
        __syncthreads();
    }

    if (tid < 128) {
        const int d = tid & 63;
        const float* P = (tid < 64) ? Pk : Pv;
        const float* W = (tid < 64) ? WkH : WvH;
        float ss = 0.f, sm = 0.f;
        #pragma unroll 8
        for (int c = 0; c < CC; c += 4) {
            float4 p = *(const float4*)(P + (size_t)d * CC + c);
            float4 w = *(const float4*)(W + (size_t)d * CC + c);
            float4 s4 = *(const float4*)&sus[c];
            ss = fmaf(p.x, w.x, ss); ss = fmaf(p.y, w.y, ss);
            ss = fmaf(p.z, w.z, ss); ss = fmaf(p.w, w.w, ss);
            sm = fmaf(w.x, s4.x, sm); sm = fmaf(w.y, s4.y, sm);
            sm = fmaf(w.z, s4.z, sm); sm = fmaf(w.w, s4.w, sm);
        }
        const float m = sm * invN;
        const float r = rsqrtf(ss * invN - m * m + 1e-5f);
        if (tid < 64) { mk[d] = m; rk[d] = r; }
        else          { mv[d] = m; rv[d] = r; }
    }
    __syncthreads();

    float* op = g_kvhat + (size_t)bh * DD * DD;
    #pragma unroll
    for (int i = 0; i < 4; i++) {
        const int d = ty * 4 + i;
        #pragma unroll
        for (int j = 0; j < 4; j++) {
            const int e = tx * 4 + j;
            op[d * DD + e] = rk[d] * rv[e] * (acc[i][j] * invN - mk[d] * mv[e]);
        }
    }
}

// ---------------------------------------------------------------------------
// k3_T: T[b][c][h*64+e] = sum_d Wq[h*64+d][c] * kvhat[d][e]
// ---------------------------------------------------------------------------
__global__ __launch_bounds__(256) void k3_T(const float* __restrict__ Wq) {
    __shared__ float kvs[DD][DD];
    const int bh = blockIdx.x;
    const int b = bh >> 3, h = bh & 7;
    const int tid = threadIdx.x;

    for (int idx = tid; idx < DD * DD; idx += 256)
        kvs[idx >> 6][idx & 63] = g_kvhat[(size_t)bh * DD * DD + idx];
    __syncthreads();

    float accT[64];
    #pragma unroll
    for (int e = 0; e < 64; e++) accT[e] = 0.f;
    const int c = tid;
    #pragma unroll 8
    for (int d = 0; d < DD; d++) {
        const float wq = Wq[(size_t)(h * DD + d) * CC + c];
        #pragma unroll
        for (int e4 = 0; e4 < 16; e4++) {
            float4 t = *(const float4*)&kvs[d][e4 * 4];
            accT[e4*4+0] = fmaf(wq, t.x, accT[e4*4+0]);
            accT[e4*4+1] = fmaf(wq, t.y, accT[e4*4+1]);
            accT[e4*4+2] = fmaf(wq, t.z, accT[e4*4+2]);
            accT[e4*4+3] = fmaf(wq, t.w, accT[e4*4+3]);
        }
    }
    float* Tp = g_T + ((size_t)b * CC + c) * HD + h * DD;
    #pragma unroll
    for (int e = 0; e < 64; e++) Tp[e] = accT[e];
}

// ---------------------------------------------------------------------------
// k3c_F: F[b] (256x256, [c][o]) = T[b] (256x512) @ Wo^T.
// grid (4 otiles, 4 ctiles, B), 64x64 tiles, K=512 step 16, prefetched.
// ---------------------------------------------------------------------------
__global__ __launch_bounds__(256) void k3c_F(const float* __restrict__ Wo) {
    __shared__ float As[16][68];
    __shared__ float Bs[16][68];
    const int o0 = blockIdx.x * 64;
    const int c0 = blockIdx.y * 64;
    const int b  = blockIdx.z;
    const int tid = threadIdx.x;
    const int tx = tid & 15, ty = tid >> 4;
    const int ar = tid >> 2, akq = (tid & 3) * 4;

    const float* Tb = g_T + (size_t)b * CC * HD;

    float acc[4][4];
    #pragma unroll
    for (int i = 0; i < 4; i++)
        #pragma unroll
        for (int j = 0; j < 4; j++) acc[i][j] = 0.f;

    float4 tA = *(const float4*)(Tb + (size_t)(c0 + ar) * HD + akq);
    float4 tB = *(const float4*)(Wo + (size_t)(o0 + ar) * HD + akq);

    for (int j0 = 0; j0 < HD; j0 += 16) {
        As[akq + 0][ar] = tA.x; As[akq + 1][ar] = tA.y;
        As[akq + 2][ar] = tA.z; As[akq + 3][ar] = tA.w;
        Bs[akq + 0][ar] = tB.x; Bs[akq + 1][ar] = tB.y;
        Bs[akq + 2][ar] = tB.z; Bs[akq + 3][ar] = tB.w;
        __syncthreads();
        if (j0 + 16 < HD) {
            tA = *(const float4*)(Tb + (size_t)(c0 + ar) * HD + j0 + 16 + akq);
            tB = *(const float4*)(Wo + (size_t)(o0 + ar) * HD + j0 + 16 + akq);
        }
        #pragma unroll
        for (int k = 0; k < 16; k++) {
            float4 a4 = *(const float4*)&As[k][ty * 4];
            float4 b4 = *(const float4*)&Bs[k][tx * 4];
            float aa[4] = {a4.x, a4.y, a4.z, a4.w};
            float bb[4] = {b4.x, b4.y, b4.z, b4.w};
            #pragma unroll
            for (int i = 0; i < 4; i++)
                #pragma unroll
                for (int j = 0; j < 4; j++)
                    acc[i][j] = fmaf(aa[i], bb[j], acc[i][j]);
        }
        __syncthreads();
    }

    #pragma unroll
    for (int i = 0; i < 4; i++)
        #pragma unroll
        for (int j = 0; j < 4; j++)
            g_F[((size_t)b * CC + c0 + ty * 4 + i) * OUTC + o0 + tx * 4 + j] = acc[i][j];
}

// ---------------------------------------------------------------------------
// k4_mma: out = U @ F + bo using mma.sync tf32 (verified R5).
// ---------------------------------------------------------------------------
__global__ __launch_bounds__(256) void k4_mma(const float* __restrict__ U,
                                              const float* __restrict__ bo,
                                              float* __restrict__ out) {
    __shared__ unsigned As[32][132];
    __shared__ unsigned Bs[32][132];

    const int tid = threadIdx.x;
    const int wid = tid >> 5, lane = tid & 31;
    const int warp_m = wid & 3;
    const int warp_n = wid >> 2;
    const int gr = lane >> 2;
    const int tc = lane & 3;

    const int n0  = blockIdx.x * 128;
    const int mt0 = blockIdx.y * 128;
    const int b   = mt0 >> 14;
    const float* Fp = g_F + (size_t)b * CC * OUTC;

    float acc[2][8][4];
    #pragma unroll
    for (int mi = 0; mi < 2; mi++)
        #pragma unroll
        for (int ni = 0; ni < 8; ni++)
            #pragma unroll
            for (int q = 0; q < 4; q++) acc[mi][ni][q] = 0.f;

    const int am  = tid >> 3;
    const int akq = (tid & 7) * 4;
    const int bk  = tid >> 5;
    const int bnq = (tid & 31) * 4;

    for (int c = 0; c < 8; c++) {
        const int k0 = c * 32;
        #pragma unroll
        for (int p = 0; p < 4; p++) {
            const int m = am + p * 32;
            float4 v = *(const float4*)(U + (size_t)(mt0 + m) * CC + k0 + akq);
            As[akq + 0][m] = to_tf32(v.x);
            As[akq + 1][m] = to_tf32(v.y);
            As[akq + 2][m] = to_tf32(v.z);
            As[akq + 3][m] = to_tf32(v.w);
        }
        #pragma unroll
        for (int p = 0; p < 4; p++) {
            const int k = bk + p * 8;
            float4 v = *(const float4*)(Fp + (size_t)(k0 + k) * OUTC + n0 + bnq);
            uint4 t;
            t.x = to_tf32(v.x); t.y = to_tf32(v.y);
            t.z = to_tf32(v.z); t.w = to_tf32(v.w);
            *(uint4*)&Bs[k][bnq] = t;
        }
        __syncthreads();

        #pragma unroll
        for (int ks = 0; ks < 4; ks++) {
            const int k8 = ks * 8;
            unsigned a[2][4];
            #pragma unroll
            for (int mi = 0; mi < 2; mi++) {
                const int mr = warp_m * 32 + mi * 16;
                a[mi][0] = As[k8 + tc][mr + gr];
                a[mi][1] = As[k8 + tc][mr + gr + 8];
                a[mi][2] = As[k8 + tc + 4][mr + gr];
                a[mi][3] = As[k8 + tc + 4][mr + gr + 8];
            }
            #pragma unroll
            for (int ni = 0; ni < 8; ni++) {
                const int nb = warp_n * 64 + ni * 8;
                unsigned b0 = Bs[k8 + tc][nb + gr];
                unsigned b1 = Bs[k8 + tc + 4][nb + gr];
                #pragma unroll
                for (int mi = 0; mi < 2; mi++)
                    MMA8(acc[mi][ni], a[mi][0], a[mi][1], a[mi][2], a[mi][3], b0, b1);
            }
        }
        __syncthreads();
    }

    #pragma unroll
    for (int mi = 0; mi < 2; mi++) {
        const int row = mt0 + warp_m * 32 + mi * 16 + gr;
        #pragma unroll
        for (int ni = 0; ni < 8; ni++) {
            const int col = n0 + warp_n * 64 + ni * 8 + tc * 2;
            const float2 bb = *(const float2*)(bo + col);
            float2 o0, o1;
            o0.x = acc[mi][ni][0] + bb.x;
            o0.y = acc[mi][ni][1] + bb.y;
            o1.x = acc[mi][ni][2] + bb.x;
            o1.y = acc[mi][ni][3] + bb.y;
            *(float2*)(out + (size_t)row * OUTC + col) = o0;
            *(float2*)(out + (size_t)(row + 8) * OUTC + col) = o1;
        }
    }
}

// ---------------------------------------------------------------------------
extern "C" void kernel_launch(void* const* d_in, const int* in_sizes, int n_in,
                              void* d_out, int out_size) {
    const float* u  = (const float*)d_in[0];
    // d_in[1] = pos_src -- unused by the reference computation
    const float* Wq = (const float*)d_in[2];
    const float* Wk = (const float*)d_in[3];
    const float* Wv = (const float*)d_in[4];
    const float* Wo = (const float*)d_in[5];
    const float* bo = (const float*)d_in[6];
    float* out = (float*)d_out;

    k_g  <<<dim3(3, NCH, BB), 256>>>(u);
    kA   <<<dim3(CC, BB), 256>>>();
    kA2  <<<dim3(128, BB), 128>>>();
    kB1  <<<dim3(BB * HH, 2, 4), 256>>>(Wk, Wv);
    kB2  <<<BB * HH, 256>>>(Wk, Wv);
    k3_T <<<BB * HH, 256>>>(Wq);
    k3c_F<<<dim3(4, 4, BB), 256>>>(Wo);
    k4_mma<<<dim3(2, 512), 256>>>(u, bo, out);
}

// round 7
// speedup vs baseline: 5.2401x; 1.0227x over previous
#include <cuda_runtime.h>
#include <cstdint>

#define BB 4
#define NN 16384
#define CC 256
#define HH 8
#define DD 64
#define HD 512
#define OUTC 256
#define NCH 32           // split-K chunks over the grid axis for G
#define KCH 512          // tokens per chunk

// static device scratch
__device__ float g_Gp[BB*NCH*CC*CC];     // per-chunk partials of G = U^T U
__device__ float g_sup[BB*NCH*CC];       // per-chunk column sums of U
__device__ float g_G[BB*CC*CC];          // reduced Gram matrices
__device__ float g_su[BB*CC];            // reduced column sums
__device__ float g_P[2*BB*HH*DD*CC];     // P[leg][bh] = W_h @ G   (64 x 256)
__device__ float g_T[BB*CC*HD];          // Wq_h^T @ kvhat, [b][c][h*64+e]
__device__ float g_F[BB*CC*OUTC];        // F per batch: [c][o]

__device__ __forceinline__ unsigned to_tf32(float v) {
    unsigned t;
    asm("cvt.rna.tf32.f32 %0, %1;" : "=r"(t) : "f"(v));
    return t;
}
__device__ __forceinline__ unsigned smem_u32(const void* p) {
    unsigned a;
    asm("{ .reg .u64 t; cvta.to.shared.u64 t, %1; cvt.u32.u64 %0, t; }" : "=r"(a) : "l"(p));
    return a;
}
#define CP_ASYNC16(dst, src) \
    asm volatile("cp.async.cg.shared.global [%0], [%1], 16;" :: "r"(dst), "l"(src))
#define CP_COMMIT() asm volatile("cp.async.commit_group;" ::: "memory")
#define CP_WAIT1()  asm volatile("cp.async.wait_group 1;" ::: "memory")
#define CP_WAIT0()  asm volatile("cp.async.wait_group 0;" ::: "memory")

#define MMA8(accp, a0, a1, a2, a3, b0, b1) \
    asm volatile( \
        "mma.sync.aligned.m16n8k8.row.col.f32.tf32.tf32.f32 " \
        "{%0,%1,%2,%3}, {%4,%5,%6,%7}, {%8,%9}, {%0,%1,%2,%3};" \
        : "+f"((accp)[0]), "+f"((accp)[1]), "+f"((accp)[2]), "+f"((accp)[3]) \
        : "r"(a0), "r"(a1), "r"(a2), "r"(a3), "r"(b0), "r"(b1))

// ---------------------------------------------------------------------------
// k_g: split-K syrk partials via tf32x3 mma (fp32-accurate Gram).
// grid (3 tiles, NCH, BB); tile -> quadrant (0,0),(0,1),(1,1).
// Diagonal quadrants load only their 128-channel half; next-slab global
// loads are prefetched into registers before the mma section.
// ---------------------------------------------------------------------------
__global__ __launch_bounds__(256) void k_g(const float* __restrict__ U) {
    __shared__ unsigned Hi[16][260];
    __shared__ unsigned Lo[16][260];
    const int tile = blockIdx.x;            // 0..2
    const int ti = tile >> 1, tj = (tile + 1) >> 1;
    const int ch = blockIdx.y, b = blockIdx.z;
    const int tid = threadIdx.x;
    const int wid = tid >> 5, lane = tid & 31;
    const int warp_m = wid & 3, warp_n = wid >> 2;
    const int gr = lane >> 2, tc = lane & 3;
    const bool diag = (ti == tj);

    const float* Up = U + (size_t)(b * NN + ch * KCH) * CC;

    float acc[2][8][4];
    #pragma unroll
    for (int mi = 0; mi < 2; mi++)
        #pragma unroll
        for (int ni = 0; ni < 8; ni++)
            #pragma unroll
            for (int q = 0; q < 4; q++) acc[mi][ni][q] = 0.f;
    float s = 0.f;

    const int lrow = tid >> 4;                                  // token row 0..15
    const int c0 = diag ? (ti * 128 + (tid & 15) * 8)           // 8 channels
                        : ((tid & 15) * 16);                    // 16 channels
    const int nq = diag ? 2 : 4;

    float4 v[4];
    {
        const float* Ut = Up + (size_t)lrow * CC + c0;
        if (diag) { v[0] = *(const float4*)Ut; v[1] = *(const float4*)(Ut + 4); }
        else {
            #pragma unroll
            for (int q = 0; q < 4; q++) v[q] = *(const float4*)(Ut + q * 4);
        }
    }

    for (int t0 = 0; t0 < KCH; t0 += 16) {
        __syncthreads();
        #pragma unroll
        for (int q = 0; q < 4; q++) {
            if (q >= nq) break;
            uint4 h, l;
            h.x = to_tf32(v[q].x); l.x = to_tf32(v[q].x - __uint_as_float(h.x));
            h.y = to_tf32(v[q].y); l.y = to_tf32(v[q].y - __uint_as_float(h.y));
            h.z = to_tf32(v[q].z); l.z = to_tf32(v[q].z - __uint_as_float(h.z));
            h.w = to_tf32(v[q].w); l.w = to_tf32(v[q].w - __uint_as_float(h.w));
            *(uint4*)&Hi[lrow][c0 + q * 4] = h;
            *(uint4*)&Lo[lrow][c0 + q * 4] = l;
        }
        __syncthreads();

        if (t0 + 16 < KCH) {
            const float* Ut = Up + (size_t)(t0 + 16 + lrow) * CC + c0;
            if (diag) { v[0] = *(const float4*)Ut; v[1] = *(const float4*)(Ut + 4); }
            else {
                #pragma unroll
                for (int q = 0; q < 4; q++) v[q] = *(const float4*)(Ut + q * 4);
            }
        }

        if (tile == 1) {
            #pragma unroll
            for (int k = 0; k < 16; k++)
                s += __uint_as_float(Hi[k][tid]) + __uint_as_float(Lo[k][tid]);
        }

        #pragma unroll
        for (int ks = 0; ks < 2; ks++) {
            const int k8 = ks * 8;
            unsigned ah[2][4], al[2][4];
            #pragma unroll
            for (int mi = 0; mi < 2; mi++) {
                const int am = ti * 128 + warp_m * 16 + mi * 64;
                ah[mi][0] = Hi[k8 + tc][am + gr];
                ah[mi][1] = Hi[k8 + tc][am + gr + 8];
                ah[mi][2] = Hi[k8 + tc + 4][am + gr];
                ah[mi][3] = Hi[k8 + tc + 4][am + gr + 8];
                al[mi][0] = Lo[k8 + tc][am + gr];
                al[mi][1] = Lo[k8 + tc][am + gr + 8];
                al[mi][2] = Lo[k8 + tc + 4][am + gr];
                al[mi][3] = Lo[k8 + tc + 4][am + gr + 8];
            }
            #pragma unroll
            for (int ni = 0; ni < 8; ni++) {
                const int nb = warp_n * 8 + ni * 16;
                const int bn = tj * 128 + nb;
                unsigned bh0 = Hi[k8 + tc][bn + gr];
                unsigned bh1 = Hi[k8 + tc + 4][bn + gr];
                unsigned bl0 = Lo[k8 + tc][bn + gr];
                unsigned bl1 = Lo[k8 + tc + 4][bn + gr];
                #pragma unroll
                for (int mi = 0; mi < 2; mi++) {
                    const int mr = warp_m * 16 + mi * 64;
                    if (diag && (nb + 8 <= mr)) continue;
                    MMA8(acc[mi][ni], ah[mi][0], ah[mi][1], ah[mi][2], ah[mi][3], bh0, bh1);
                    MMA8(acc[mi][ni], ah[mi][0], ah[mi][1], ah[mi][2], ah[mi][3], bl0, bl1);
                    MMA8(acc[mi][ni], al[mi][0], al[mi][1], al[mi][2], al[mi][3], bh0, bh1);
                }
            }
        }
    }

    float* op = g_Gp + (size_t)(b * NCH + ch) * CC * CC;
    #pragma unroll
    for (int mi = 0; mi < 2; mi++) {
        const int mr = warp_m * 16 + mi * 64;
        #pragma unroll
        for (int ni = 0; ni < 8; ni++) {
            const int nb = warp_n * 8 + ni * 16;
            if (diag && (nb + 8 <= mr)) continue;
            const int row = ti * 128 + mr + gr;
            const int col = tj * 128 + nb + tc * 2;
            float2 c0v = make_float2(acc[mi][ni][0], acc[mi][ni][1]);
            float2 c1v = make_float2(acc[mi][ni][2], acc[mi][ni][3]);
            *(float2*)(op + (size_t)row * CC + col) = c0v;
            *(float2*)(op + (size_t)(row + 8) * CC + col) = c1v;
        }
    }
    if (tile == 1) g_sup[(size_t)(b * NCH + ch) * CC + tid] = s;
}

// ---------------------------------------------------------------------------
// kA: reduce split-K partials -> g_G, g_su, reconstructing un-stored
// positions via symmetry (read the transposed, computed slot).
// ---------------------------------------------------------------------------
__global__ __launch_bounds__(256) void kA() {
    const int r = blockIdx.x, b = blockIdx.y, c = threadIdx.x;
    int rr = r, cc = c;
    const bool swap = ((r >= 128) && (c < 128)) ||
                      (((r >= 128) == (c >= 128)) && (c < r));
    if (swap) { rr = c; cc = r; }
    float s = 0.f;
    for (int ch = 0; ch < NCH; ch++)
        s += g_Gp[((size_t)(b * NCH + ch) * CC + rr) * CC + cc];
    g_G[((size_t)b * CC + r) * CC + c] = s;
    if (r == 0) {
        float t = 0.f;
        for (int ch = 0; ch < NCH; ch++)
            t += g_sup[(size_t)(b * NCH + ch) * CC + c];
        g_su[(size_t)b * CC + c] = t;
    }
}

// ---------------------------------------------------------------------------
// kB1: P[leg][b,h] = W_h @ G. grid (32 bh, 2 legs, 4 otiles) = 256 blocks.
// ---------------------------------------------------------------------------
__global__ __launch_bounds__(256) void kB1(const float* __restrict__ Wk,
                                           const float* __restrict__ Wv) {
    __shared__ float As[16][68];
    __shared__ float Bs[16][68];
    const int bh = blockIdx.x, leg = blockIdx.y, ot = blockIdx.z;
    const int b = bh >> 3, h = bh & 7;
    const float* W  = (leg ? Wv : Wk) + (size_t)h * DD * CC;
    const float* Gb = g_G + (size_t)b * CC * CC;
    const int o0 = ot * 64;
    const int tid = threadIdx.x;
    const int tx = tid & 15, ty = tid >> 4;

    const int ad = tid >> 2, akq = (tid & 3) * 4;
    const int bk = tid >> 4, bc4 = (tid & 15) * 4;

    float acc[4][4];
    #pragma unroll
    for (int i = 0; i < 4; i++)
        #pragma unroll
        for (int j = 0; j < 4; j++) acc[i][j] = 0.f;

    float4 wA = *(const float4*)(W + (size_t)ad * CC + akq);
    float4 wB = *(const float4*)(Gb + (size_t)bk * CC + o0 + bc4);

    for (int kt = 0; kt < CC; kt += 16) {
        As[akq + 0][ad] = wA.x; As[akq + 1][ad] = wA.y;
        As[akq + 2][ad] = wA.z; As[akq + 3][ad] = wA.w;
        *(float4*)&Bs[bk][bc4] = wB;
        __syncthreads();
        if (kt + 16 < CC) {
            wA = *(const float4*)(W + (size_t)ad * CC + kt + 16 + akq);
            wB = *(const float4*)(Gb + (size_t)(kt + 16 + bk) * CC + o0 + bc4);
        }
        #pragma unroll
        for (int k = 0; k < 16; k++) {
            float4 a4 = *(const float4*)&As[k][ty * 4];
            float4 b4 = *(const float4*)&Bs[k][tx * 4];
            float aa[4] = {a4.x, a4.y, a4.z, a4.w};
            float bb[4] = {b4.x, b4.y, b4.z, b4.w};
            #pragma unroll
            for (int i = 0; i < 4; i++)
                #pragma unroll
                for (int j = 0; j < 4; j++)
                    acc[i][j] = fmaf(aa[i], bb[j], acc[i][j]);
        }
        __syncthreads();
    }

    float* op = g_P + (size_t)(leg * BB * HH + bh) * DD * CC;
    #pragma unroll
    for (int i = 0; i < 4; i++)
        #pragma unroll
        for (int j = 0; j < 4; j++)
            op[(size_t)(ty * 4 + i) * CC + o0 + tx * 4 + j] = acc[i][j];
}

// ---------------------------------------------------------------------------
// kB2T (fused kB2 + k3_T): per (b,h): kv_raw = Pk @ Wv_h^T; stats;
// normalize into smem kvs; then T[b][c][h*64+e] = sum_d Wq[hD+d][c]*kvs[d][e].
// ---------------------------------------------------------------------------
__global__ __launch_bounds__(256) void kB2T(const float* __restrict__ Wk,
                                            const float* __restrict__ Wv,
                                            const float* __restrict__ Wq) {
    __shared__ float As[16][68];
    __shared__ float Bs[16][68];
    __shared__ __align__(16) float sus[CC];
    __shared__ float mk[DD], rk[DD], mv[DD], rv[DD];
    __shared__ float kvs[DD][DD];
    const int bh = blockIdx.x;
    const int b = bh >> 3, h = bh & 7;
    const int tid = threadIdx.x;
    const int tx = tid & 15, ty = tid >> 4;
    const float invN = 1.f / NN;

    const float* Pk  = g_P + (size_t)bh * DD * CC;
    const float* Pv  = g_P + (size_t)(BB * HH + bh) * DD * CC;
    const float* WkH = Wk + (size_t)h * DD * CC;
    const float* WvH = Wv + (size_t)h * DD * CC;

    sus[tid] = g_su[(size_t)b * CC + tid];

    const int ad = tid >> 2, akq = (tid & 3) * 4;

    float acc[4][4];
    #pragma unroll
    for (int i = 0; i < 4; i++)
        #pragma unroll
        for (int j = 0; j < 4; j++) acc[i][j] = 0.f;

    float4 pA = *(const float4*)(Pk + (size_t)ad * CC + akq);
    float4 pB = *(const float4*)(WvH + (size_t)ad * CC + akq);

    for (int kt = 0; kt < CC; kt += 16) {
        As[akq + 0][ad] = pA.x; As[akq + 1][ad] = pA.y;
        As[akq + 2][ad] = pA.z; As[akq + 3][ad] = pA.w;
        Bs[akq + 0][ad] = pB.x; Bs[akq + 1][ad] = pB.y;
        Bs[akq + 2][ad] = pB.z; Bs[akq + 3][ad] = pB.w;
        __syncthreads();
        if (kt + 16 < CC) {
            pA = *(const float4*)(Pk + (size_t)ad * CC + kt + 16 + akq);
            pB = *(const float4*)(WvH + (size_t)ad * CC + kt + 16 + akq);
        }
        #pragma unroll
        for (int k = 0; k < 16; k++) {
            float4 a4 = *(const float4*)&As[k][ty * 4];
            float4 b4 = *(const float4*)&Bs[k][tx * 4];
            float aa[4] = {a4.x, a4.y, a4.z, a4.w};
            float bb[4] = {b4.x, b4.y, b4.z, b4.w};
            #pragma unroll
            for (int i = 0; i < 4; i++)
                #pragma unroll
                for (int j = 0; j < 4; j++)
                    acc[i][j] = fmaf(aa[i], bb[j], acc[i][j]);
        }
        __syncthreads();
    }

    if (tid < 128) {
        const int d = tid & 63;
        const float* P = (tid < 64) ? Pk : Pv;
        const float* W = (tid < 64) ? WkH : WvH;
        float ss = 0.f, sm = 0.f;
        #pragma unroll 8
        for (int c = 0; c < CC; c += 4) {
            float4 p = *(const float4*)(P + (size_t)d * CC + c);
            float4 w = *(const float4*)(W + (size_t)d * CC + c);
            float4 s4 = *(const float4*)&sus[c];
            ss = fmaf(p.x, w.x, ss); ss = fmaf(p.y, w.y, ss);
            ss = fmaf(p.z, w.z, ss); ss = fmaf(p.w, w.w, ss);
            sm = fmaf(w.x, s4.x, sm); sm = fmaf(w.y, s4.y, sm);
            sm = fmaf(w.z, s4.z, sm); sm = fmaf(w.w, s4.w, sm);
        }
        const float m = sm * invN;
        const float r = rsqrtf(ss * invN - m * m + 1e-5f);
        if (tid < 64) { mk[d] = m; rk[d] = r; }
        else          { mv[d] = m; rv[d] = r; }
    }
    __syncthreads();

    #pragma unroll
    for (int i = 0; i < 4; i++) {
        const int d = ty * 4 + i;
        #pragma unroll
        for (int j = 0; j < 4; j++) {
            const int e = tx * 4 + j;
            kvs[d][e] = rk[d] * rv[e] * (acc[i][j] * invN - mk[d] * mv[e]);
        }
    }
    __syncthreads();

    // --- fused k3_T ---
    float accT[64];
    #pragma unroll
    for (int e = 0; e < 64; e++) accT[e] = 0.f;
    const int c = tid;
    #pragma unroll 8
    for (int d = 0; d < DD; d++) {
        const float wq = Wq[(size_t)(h * DD + d) * CC + c];
        #pragma unroll
        for (int e4 = 0; e4 < 16; e4++) {
            float4 t = *(const float4*)&kvs[d][e4 * 4];
            accT[e4*4+0] = fmaf(wq, t.x, accT[e4*4+0]);
            accT[e4*4+1] = fmaf(wq, t.y, accT[e4*4+1]);
            accT[e4*4+2] = fmaf(wq, t.z, accT[e4*4+2]);
            accT[e4*4+3] = fmaf(wq, t.w, accT[e4*4+3]);
        }
    }
    float* Tp = g_T + ((size_t)b * CC + c) * HD + h * DD;
    #pragma unroll
    for (int e = 0; e < 64; e++) Tp[e] = accT[e];
}

// ---------------------------------------------------------------------------
// k3c_F: F[b] (256x256, [c][o]) = T[b] (256x512) @ Wo^T.
// ---------------------------------------------------------------------------
__global__ __launch_bounds__(256) void k3c_F(const float* __restrict__ Wo) {
    __shared__ float As[16][68];
    __shared__ float Bs[16][68];
    const int o0 = blockIdx.x * 64;
    const int c0 = blockIdx.y * 64;
    const int b  = blockIdx.z;
    const int tid = threadIdx.x;
    const int tx = tid & 15, ty = tid >> 4;
    const int ar = tid >> 2, akq = (tid & 3) * 4;

    const float* Tb = g_T + (size_t)b * CC * HD;

    float acc[4][4];
    #pragma unroll
    for (int i = 0; i < 4; i++)
        #pragma unroll
        for (int j = 0; j < 4; j++) acc[i][j] = 0.f;

    float4 tA = *(const float4*)(Tb + (size_t)(c0 + ar) * HD + akq);
    float4 tB = *(const float4*)(Wo + (size_t)(o0 + ar) * HD + akq);

    for (int j0 = 0; j0 < HD; j0 += 16) {
        As[akq + 0][ar] = tA.x; As[akq + 1][ar] = tA.y;
        As[akq + 2][ar] = tA.z; As[akq + 3][ar] = tA.w;
        Bs[akq + 0][ar] = tB.x; Bs[akq + 1][ar] = tB.y;
        Bs[akq + 2][ar] = tB.z; Bs[akq + 3][ar] = tB.w;
        __syncthreads();
        if (j0 + 16 < HD) {
            tA = *(const float4*)(Tb + (size_t)(c0 + ar) * HD + j0 + 16 + akq);
            tB = *(const float4*)(Wo + (size_t)(o0 + ar) * HD + j0 + 16 + akq);
        }
        #pragma unroll
        for (int k = 0; k < 16; k++) {
            float4 a4 = *(const float4*)&As[k][ty * 4];
            float4 b4 = *(const float4*)&Bs[k][tx * 4];
            float aa[4] = {a4.x, a4.y, a4.z, a4.w};
            float bb[4] = {b4.x, b4.y, b4.z, b4.w};
            #pragma unroll
            for (int i = 0; i < 4; i++)
                #pragma unroll
                for (int j = 0; j < 4; j++)
                    acc[i][j] = fmaf(aa[i], bb[j], acc[i][j]);
        }
        __syncthreads();
    }

    #pragma unroll
    for (int i = 0; i < 4; i++)
        #pragma unroll
        for (int j = 0; j < 4; j++)
            g_F[((size_t)b * CC + c0 + ty * 4 + i) * OUTC + o0 + tx * 4 + j] = acc[i][j];
}

// ---------------------------------------------------------------------------
// k4_mma: out = U @ F + bo, tf32 mma.sync with cp.async 2-stage pipeline.
// A raw fp32 in smem [m(128)][k(32+4pad)], B raw [k(32)][n(128+4pad)];
// tf32 conversion at fragment-load time (overlaps tensor pipe).
// ---------------------------------------------------------------------------
#define K4_ASTR (128 * 36)              // floats per A buffer
#define K4_BSTR (32 * 132)              // floats per B buffer
#define K4_SMEM ((2 * K4_ASTR + 2 * K4_BSTR) * 4)

__global__ __launch_bounds__(256) void k4_mma(const float* __restrict__ U,
                                              const float* __restrict__ bo,
                                              float* __restrict__ out) {
    extern __shared__ float sm4[];
    float* Asm = sm4;                    // 2 x [128][36]
    float* Bsm = sm4 + 2 * K4_ASTR;      // 2 x [32][132]
    const unsigned sbase = smem_u32(sm4);

    const int tid = threadIdx.x;
    const int wid = tid >> 5, lane = tid & 31;
    const int warp_m = wid & 3;
    const int warp_n = wid >> 2;
    const int gr = lane >> 2;
    const int tc = lane & 3;

    const int n0  = blockIdx.x * 128;
    const int mt0 = blockIdx.y * 128;
    const int b   = mt0 >> 14;
    const float* Fp = g_F + (size_t)b * CC * OUTC;

    float acc[2][8][4];
    #pragma unroll
    for (int mi = 0; mi < 2; mi++)
        #pragma unroll
        for (int ni = 0; ni < 8; ni++)
            #pragma unroll
            for (int q = 0; q < 4; q++) acc[mi][ni][q] = 0.f;

    const int am  = tid >> 3;            // 0..31 (+p*32)
    const int akq = (tid & 7) * 4;       // 0..28
    const int bk  = tid >> 5;            // 0..7  (+p*8)
    const int bnq = (tid & 31) * 4;      // 0..124

    // issue chunk c into buffer buf
    auto issue = [&](int c, int buf) {
        const float* Ag = U + (size_t)mt0 * CC + c * 32;
        #pragma unroll
        for (int p = 0; p < 4; p++) {
            const int m = am + p * 32;
            unsigned dst = sbase + (unsigned)(buf * K4_ASTR + m * 36 + akq) * 4u;
            CP_ASYNC16(dst, Ag + (size_t)m * CC + akq);
        }
        const float* Bg = Fp + (size_t)(c * 32) * OUTC + n0;
        #pragma unroll
        for (int p = 0; p < 4; p++) {
            const int k = bk + p * 8;
            unsigned dst = sbase + (unsigned)(2 * K4_ASTR + buf * K4_BSTR + k * 132 + bnq) * 4u;
            CP_ASYNC16(dst, Bg + (size_t)k * OUTC + bnq);
        }
        CP_COMMIT();
    };

    issue(0, 0);

    for (int c = 0; c < 8; c++) {
        const int buf = c & 1;
        if (c < 7) { issue(c + 1, buf ^ 1); CP_WAIT1(); }
        else       { CP_WAIT0(); }
        __syncthreads();

        const float* Ab = Asm + buf * K4_ASTR;
        const float* Bb = Bsm + buf * K4_BSTR;

        #pragma unroll
        for (int ks = 0; ks < 4; ks++) {
            const int k8 = ks * 8;
            unsigned a[2][4];
            #pragma unroll
            for (int mi = 0; mi < 2; mi++) {
                const int mr = warp_m * 32 + mi * 16;
                a[mi][0] = to_tf32(Ab[(mr + gr) * 36 + k8 + tc]);
                a[mi][1] = to_tf32(Ab[(mr + gr + 8) * 36 + k8 + tc]);
                a[mi][2] = to_tf32(Ab[(mr + gr) * 36 + k8 + tc + 4]);
                a[mi][3] = to_tf32(Ab[(mr + gr + 8) * 36 + k8 + tc + 4]);
            }
            #pragma unroll
            for (int ni = 0; ni < 8; ni++) {
                const int nb = warp_n * 64 + ni * 8;
                unsigned b0 = to_tf32(Bb[(k8 + tc) * 132 + nb + gr]);
                unsigned b1 = to_tf32(Bb[(k8 + tc + 4) * 132 + nb + gr]);
                #pragma unroll
                for (int mi = 0; mi < 2; mi++)
                    MMA8(acc[mi][ni], a[mi][0], a[mi][1], a[mi][2], a[mi][3], b0, b1);
            }
        }
        __syncthreads();
    }

    #pragma unroll
    for (int mi = 0; mi < 2; mi++) {
        const int row = mt0 + warp_m * 32 + mi * 16 + gr;
        #pragma unroll
        for (int ni = 0; ni < 8; ni++) {
            const int col = n0 + warp_n * 64 + ni * 8 + tc * 2;
            const float2 bb = *(const float2*)(bo + col);
            float2 o0, o1;
            o0.x = acc[mi][ni][0] + bb.x;
            o0.y = acc[mi][ni][1] + bb.y;
            o1.x = acc[mi][ni][2] + bb.x;
            o1.y = acc[mi][ni][3] + bb.y;
            *(float2*)(out + (size_t)row * OUTC + col) = o0;
            *(float2*)(out + (size_t)(row + 8) * OUTC + col) = o1;
        }
    }
}

// ---------------------------------------------------------------------------
extern "C" void kernel_launch(void* const* d_in, const int* in_sizes, int n_in,
                              void* d_out, int out_size) {
    const float* u  = (const float*)d_in[0];
    // d_in[1] = pos_src -- unused by the reference computation
    const float* Wq = (const float*)d_in[2];
    const float* Wk = (const float*)d_in[3];
    const float* Wv = (const float*)d_in[4];
    const float* Wo = (const float*)d_in[5];
    const float* bo = (const float*)d_in[6];
    float* out = (float*)d_out;

    static int smem_set = 0;
    if (!smem_set) {
        cudaFuncSetAttribute(k4_mma, cudaFuncAttributeMaxDynamicSharedMemorySize, K4_SMEM);
        smem_set = 1;
    }

    k_g  <<<dim3(3, NCH, BB), 256>>>(u);
    kA   <<<dim3(CC, BB), 256>>>();
    kB1  <<<dim3(BB * HH, 2, 4), 256>>>(Wk, Wv);
    kB2T <<<BB * HH, 256>>>(Wk, Wv, Wq);
    k3c_F<<<dim3(4, 4, BB), 256>>>(Wo);
    k4_mma<<<dim3(2, 512), 256, K4_SMEM>>>(u, bo, out);
}

// round 9
// speedup vs baseline: 6.7936x; 1.2965x over previous
#include <cuda_runtime.h>
#include <cstdint>

#define BB 4
#define NN 16384
#define CC 256
#define HH 8
#define DD 64
#define HD 512
#define OUTC 256
#define NCH 32           // split-K chunks over the grid axis for G
#define KCH 512          // tokens per chunk

// static device scratch
__device__ float g_Gp[BB*NCH*CC*CC];     // per-chunk partials of G = U^T U
__device__ float g_sup[BB*NCH*CC];       // per-chunk column sums of U
__device__ float g_G[BB*CC*CC];          // reduced Gram matrices
__device__ float g_su[BB*CC];            // reduced column sums
__device__ float g_P[2*BB*HH*DD*CC];     // P[leg][bh] = W_h @ G   (64 x 256)
__device__ float g_T[BB*CC*HD];          // Wq_h^T @ kvhat, [b][c][h*64+e]
__device__ float g_F[BB*CC*OUTC];        // F per batch: [c][o]

__device__ __forceinline__ unsigned to_tf32(float v) {
    unsigned t;
    asm("cvt.rna.tf32.f32 %0, %1;" : "=r"(t) : "f"(v));
    return t;
}
__device__ __forceinline__ unsigned smem_u32(const void* p) {
    unsigned a;
    asm("{ .reg .u64 t; cvta.to.shared.u64 t, %1; cvt.u32.u64 %0, t; }" : "=r"(a) : "l"(p));
    return a;
}
#define CP_ASYNC16(dst, src) \
    asm volatile("cp.async.cg.shared.global [%0], [%1], 16;" :: "r"(dst), "l"(src))
#define CP_COMMIT() asm volatile("cp.async.commit_group;" ::: "memory")
#define CP_WAIT1()  asm volatile("cp.async.wait_group 1;" ::: "memory")
#define CP_WAIT0()  asm volatile("cp.async.wait_group 0;" ::: "memory")

#define MMA8(accp, a0, a1, a2, a3, b0, b1) \
    asm volatile( \
        "mma.sync.aligned.m16n8k8.row.col.f32.tf32.tf32.f32 " \
        "{%0,%1,%2,%3}, {%4,%5,%6,%7}, {%8,%9}, {%0,%1,%2,%3};" \
        : "+f"((accp)[0]), "+f"((accp)[1]), "+f"((accp)[2]), "+f"((accp)[3]) \
        : "r"(a0), "r"(a1), "r"(a2), "r"(a3), "r"(b0), "r"(b1))

// ---------------------------------------------------------------------------
// k_g: split-K syrk partials via tf32 mma (single-term).
// grid (3 tiles, NCH, BB); tile -> quadrant (0,0),(0,1),(1,1).
// Diagonal quadrants load only their 128-channel half; next-slab global
// loads are prefetched into registers before the mma section.
// ---------------------------------------------------------------------------
__global__ __launch_bounds__(256) void k_g(const float* __restrict__ U) {
    __shared__ unsigned Hi[16][260];
    const int tile = blockIdx.x;            // 0..2
    const int ti = tile >> 1, tj = (tile + 1) >> 1;
    const int ch = blockIdx.y, b = blockIdx.z;
    const int tid = threadIdx.x;
    const int wid = tid >> 5, lane = tid & 31;
    const int warp_m = wid & 3, warp_n = wid >> 2;
    const int gr = lane >> 2, tc = lane & 3;
    const bool diag = (ti == tj);

    const float* Up = U + (size_t)(b * NN + ch * KCH) * CC;

    float acc[2][8][4];
    #pragma unroll
    for (int mi = 0; mi < 2; mi++)
        #pragma unroll
        for (int ni = 0; ni < 8; ni++)
            #pragma unroll
            for (int q = 0; q < 4; q++) acc[mi][ni][q] = 0.f;
    float s = 0.f;

    const int lrow = tid >> 4;                                  // token row 0..15
    const int c0 = diag ? (ti * 128 + (tid & 15) * 8)           // 8 channels
                        : ((tid & 15) * 16);                    // 16 channels
    const int nq = diag ? 2 : 4;

    float4 v[4];
    {
        const float* Ut = Up + (size_t)lrow * CC + c0;
        if (diag) { v[0] = *(const float4*)Ut; v[1] = *(const float4*)(Ut + 4); }
        else {
            #pragma unroll
            for (int q = 0; q < 4; q++) v[q] = *(const float4*)(Ut + q * 4);
        }
    }

    for (int t0 = 0; t0 < KCH; t0 += 16) {
        __syncthreads();
        #pragma unroll
        for (int q = 0; q < 4; q++) {
            if (q >= nq) break;
            uint4 h;
            h.x = to_tf32(v[q].x);
            h.y = to_tf32(v[q].y);
            h.z = to_tf32(v[q].z);
            h.w = to_tf32(v[q].w);
            *(uint4*)&Hi[lrow][c0 + q * 4] = h;
        }
        __syncthreads();

        if (t0 + 16 < KCH) {
            const float* Ut = Up + (size_t)(t0 + 16 + lrow) * CC + c0;
            if (diag) { v[0] = *(const float4*)Ut; v[1] = *(const float4*)(Ut + 4); }
            else {
                #pragma unroll
                for (int q = 0; q < 4; q++) v[q] = *(const float4*)(Ut + q * 4);
            }
        }

        if (tile == 1) {
            #pragma unroll
            for (int k = 0; k < 16; k++)
                s += __uint_as_float(Hi[k][tid]);
        }

        #pragma unroll
        for (int ks = 0; ks < 2; ks++) {
            const int k8 = ks * 8;
            unsigned ah[2][4];
            #pragma unroll
            for (int mi = 0; mi < 2; mi++) {
                const int am = ti * 128 + warp_m * 16 + mi * 64;
                ah[mi][0] = Hi[k8 + tc][am + gr];
                ah[mi][1] = Hi[k8 + tc][am + gr + 8];
                ah[mi][2] = Hi[k8 + tc + 4][am + gr];
                ah[mi][3] = Hi[k8 + tc + 4][am + gr + 8];
            }
            #pragma unroll
            for (int ni = 0; ni < 8; ni++) {
                const int nb = warp_n * 8 + ni * 16;
                const int bn = tj * 128 + nb;
                unsigned bh0 = Hi[k8 + tc][bn + gr];
                unsigned bh1 = Hi[k8 + tc + 4][bn + gr];
                #pragma unroll
                for (int mi = 0; mi < 2; mi++) {
                    const int mr = warp_m * 16 + mi * 64;
                    if (diag && (nb + 8 <= mr)) continue;
                    MMA8(acc[mi][ni], ah[mi][0], ah[mi][1], ah[mi][2], ah[mi][3], bh0, bh1);
                }
            }
        }
    }

    float* op = g_Gp + (size_t)(b * NCH + ch) * CC * CC;
    #pragma unroll
    for (int mi = 0; mi < 2; mi++) {
        const int mr = warp_m * 16 + mi * 64;
        #pragma unroll
        for (int ni = 0; ni < 8; ni++) {
            const int nb = warp_n * 8 + ni * 16;
            if (diag && (nb + 8 <= mr)) continue;
            const int row = ti * 128 + mr + gr;
            const int col = tj * 128 + nb + tc * 2;
            float2 c0v = make_float2(acc[mi][ni][0], acc[mi][ni][1]);
            float2 c1v = make_float2(acc[mi][ni][2], acc[mi][ni][3]);
            *(float2*)(op + (size_t)row * CC + col) = c0v;
            *(float2*)(op + (size_t)(row + 8) * CC + col) = c1v;
        }
    }
    if (tile == 1) g_sup[(size_t)(b * NCH + ch) * CC + tid] = s;
}

// ---------------------------------------------------------------------------
// kA: reduce split-K partials -> g_G, g_su, reconstructing un-stored
// positions via symmetry (read the transposed, computed slot).
// ---------------------------------------------------------------------------
__global__ __launch_bounds__(256) void kA() {
    const int r = blockIdx.x, b = blockIdx.y, c = threadIdx.x;
    int rr = r, cc = c;
    const bool swap = ((r >= 128) && (c < 128)) ||
                      (((r >= 128) == (c >= 128)) && (c < r));
    if (swap) { rr = c; cc = r; }
    float s = 0.f;
    for (int ch = 0; ch < NCH; ch++)
        s += g_Gp[((size_t)(b * NCH + ch) * CC + rr) * CC + cc];
    g_G[((size_t)b * CC + r) * CC + c] = s;
    if (r == 0) {
        float t = 0.f;
        for (int ch = 0; ch < NCH; ch++)
            t += g_sup[(size_t)(b * NCH + ch) * CC + c];
        g_su[(size_t)b * CC + c] = t;
    }
}

// ---------------------------------------------------------------------------
// kB1: P[leg][b,h] = W_h @ G. grid (32 bh, 2 legs, 4 otiles) = 256 blocks.
// ---------------------------------------------------------------------------
__global__ __launch_bounds__(256) void kB1(const float* __restrict__ Wk,
                                           const float* __restrict__ Wv) {
    __shared__ float As[16][68];
    __shared__ float Bs[16][68];
    const int bh = blockIdx.x, leg = blockIdx.y, ot = blockIdx.z;
    const int b = bh >> 3, h = bh & 7;
    const float* W  = (leg ? Wv : Wk) + (size_t)h * DD * CC;
    const float* Gb = g_G + (size_t)b * CC * CC;
    const int o0 = ot * 64;
    const int tid = threadIdx.x;
    const int tx = tid & 15, ty = tid >> 4;

    const int ad = tid >> 2, akq = (tid & 3) * 4;
    const int bk = tid >> 4, bc4 = (tid & 15) * 4;

    float acc[4][4];
    #pragma unroll
    for (int i = 0; i < 4; i++)
        #pragma unroll
        for (int j = 0; j < 4; j++) acc[i][j] = 0.f;

    float4 wA = *(const float4*)(W + (size_t)ad * CC + akq);
    float4 wB = *(const float4*)(Gb + (size_t)bk * CC + o0 + bc4);

    for (int kt = 0; kt < CC; kt += 16) {
        As[akq + 0][ad] = wA.x; As[akq + 1][ad] = wA.y;
        As[akq + 2][ad] = wA.z; As[akq + 3][ad] = wA.w;
        *(float4*)&Bs[bk][bc4] = wB;
        __syncthreads();
        if (kt + 16 < CC) {
            wA = *(const float4*)(W + (size_t)ad * CC + kt + 16 + akq);
            wB = *(const float4*)(Gb + (size_t)(kt + 16 + bk) * CC + o0 + bc4);
        }
        #pragma unroll
        for (int k = 0; k < 16; k++) {
            float4 a4 = *(const float4*)&As[k][ty * 4];
            float4 b4 = *(const float4*)&Bs[k][tx * 4];
            float aa[4] = {a4.x, a4.y, a4.z, a4.w};
            float bb[4] = {b4.x, b4.y, b4.z, b4.w};
            #pragma unroll
            for (int i = 0; i < 4; i++)
                #pragma unroll
                for (int j = 0; j < 4; j++)
                    acc[i][j] = fmaf(aa[i], bb[j], acc[i][j]);
        }
        __syncthreads();
    }

    float* op = g_P + (size_t)(leg * BB * HH + bh) * DD * CC;
    #pragma unroll
    for (int i = 0; i < 4; i++)
        #pragma unroll
        for (int j = 0; j < 4; j++)
            op[(size_t)(ty * 4 + i) * CC + o0 + tx * 4 + j] = acc[i][j];
}

// ---------------------------------------------------------------------------
// kB2T (fused kB2 + k3_T): per (b,h): kv_raw = Pk @ Wv_h^T; stats;
// normalize into smem kvs; then T[b][c][h*64+e] = sum_d Wq[hD+d][c]*kvs[d][e].
// ---------------------------------------------------------------------------
__global__ __launch_bounds__(256) void kB2T(const float* __restrict__ Wk,
                                            const float* __restrict__ Wv,
                                            const float* __restrict__ Wq) {
    __shared__ float As[16][68];
    __shared__ float Bs[16][68];
    __shared__ __align__(16) float sus[CC];
    __shared__ float mk[DD], rk[DD], mv[DD], rv[DD];
    __shared__ float kvs[DD][DD];
    const int bh = blockIdx.x;
    const int b = bh >> 3, h = bh & 7;
    const int tid = threadIdx.x;
    const int tx = tid & 15, ty = tid >> 4;
    const float invN = 1.f / NN;

    const float* Pk  = g_P + (size_t)bh * DD * CC;
    const float* Pv  = g_P + (size_t)(BB * HH + bh) * DD * CC;
    const float* WkH = Wk + (size_t)h * DD * CC;
    const float* WvH = Wv + (size_t)h * DD * CC;

    sus[tid] = g_su[(size_t)b * CC + tid];

    const int ad = tid >> 2, akq = (tid & 3) * 4;

    float acc[4][4];
    #pragma unroll
    for (int i = 0; i < 4; i++)
        #pragma unroll
        for (int j = 0; j < 4; j++) acc[i][j] = 0.f;

    float4 pA = *(const float4*)(Pk + (size_t)ad * CC + akq);
    float4 pB = *(const float4*)(WvH + (size_t)ad * CC + akq);

    for (int kt = 0; kt < CC; kt += 16) {
        As[akq + 0][ad] = pA.x; As[akq + 1][ad] = pA.y;
        As[akq + 2][ad] = pA.z; As[akq + 3][ad] = pA.w;
        Bs[akq + 0][ad] = pB.x; Bs[akq + 1][ad] = pB.y;
        Bs[akq + 2][ad] = pB.z; Bs[akq + 3][ad] = pB.w;
        __syncthreads();
        if (kt + 16 < CC) {
            pA = *(const float4*)(Pk + (size_t)ad * CC + kt + 16 + akq);
            pB = *(const float4*)(WvH + (size_t)ad * CC + kt + 16 + akq);
        }
        #pragma unroll
        for (int k = 0; k < 16; k++) {
            float4 a4 = *(const float4*)&As[k][ty * 4];
            float4 b4 = *(const float4*)&Bs[k][tx * 4];
            float aa[4] = {a4.x, a4.y, a4.z, a4.w};
            float bb[4] = {b4.x, b4.y, b4.z, b4.w};
            #pragma unroll
            for (int i = 0; i < 4; i++)
                #pragma unroll
                for (int j = 0; j < 4; j++)
                    acc[i][j] = fmaf(aa[i], bb[j], acc[i][j]);
        }
        __syncthreads();
    }

    if (tid < 128) {
        const int d = tid & 63;
        const float* P = (tid < 64) ? Pk : Pv;
        const float* W = (tid < 64) ? WkH : WvH;
        float ss = 0.f, sm = 0.f;
        #pragma unroll 8
        for (int c = 0; c < CC; c += 4) {
            float4 p = *(const float4*)(P + (size_t)d * CC + c);
            float4 w = *(const float4*)(W + (size_t)d * CC + c);
            float4 s4 = *(const float4*)&sus[c];
            ss = fmaf(p.x, w.x, ss); ss = fmaf(p.y, w.y, ss);
            ss = fmaf(p.z, w.z, ss); ss = fmaf(p.w, w.w, ss);
            sm = fmaf(w.x, s4.x, sm); sm = fmaf(w.y, s4.y, sm);
            sm = fmaf(w.z, s4.z, sm); sm = fmaf(w.w, s4.w, sm);
        }
        const float m = sm * invN;
        const float r = rsqrtf(ss * invN - m * m + 1e-5f);
        if (tid < 64) { mk[d] = m; rk[d] = r; }
        else          { mv[d] = m; rv[d] = r; }
    }
    __syncthreads();

    #pragma unroll
    for (int i = 0; i < 4; i++) {
        const int d = ty * 4 + i;
        #pragma unroll
        for (int j = 0; j < 4; j++) {
            const int e = tx * 4 + j;
            kvs[d][e] = rk[d] * rv[e] * (acc[i][j] * invN - mk[d] * mv[e]);
        }
    }
    __syncthreads();

    // --- fused k3_T ---
    float accT[64];
    #pragma unroll
    for (int e = 0; e < 64; e++) accT[e] = 0.f;
    const int c = tid;
    #pragma unroll 8
    for (int d = 0; d < DD; d++) {
        const float wq = Wq[(size_t)(h * DD + d) * CC + c];
        #pragma unroll
        for (int e4 = 0; e4 < 16; e4++) {
            float4 t = *(const float4*)&kvs[d][e4 * 4];
            accT[e4*4+0] = fmaf(wq, t.x, accT[e4*4+0]);
            accT[e4*4+1] = fmaf(wq, t.y, accT[e4*4+1]);
            accT[e4*4+2] = fmaf(wq, t.z, accT[e4*4+2]);
            accT[e4*4+3] = fmaf(wq, t.w, accT[e4*4+3]);
        }
    }
    float* Tp = g_T + ((size_t)b * CC + c) * HD + h * DD;
    #pragma unroll
    for (int e = 0; e < 64; e++) Tp[e] = accT[e];
}

// ---------------------------------------------------------------------------
// k3c_F: F[b] (256x256, [c][o]) = T[b] (256x512) @ Wo^T.
// ---------------------------------------------------------------------------
__global__ __launch_bounds__(256) void k3c_F(const float* __restrict__ Wo) {
    __shared__ float As[16][68];
    __shared__ float Bs[16][68];
    const int o0 = blockIdx.x * 64;
    const int c0 = blockIdx.y * 64;
    const int b  = blockIdx.z;
    const int tid = threadIdx.x;
    const int tx = tid & 15, ty = tid >> 4;
    const int ar = tid >> 2, akq = (tid & 3) * 4;

    const float* Tb = g_T + (size_t)b * CC * HD;

    float acc[4][4];
    #pragma unroll
    for (int i = 0; i < 4; i++)
        #pragma unroll
        for (int j = 0; j < 4; j++) acc[i][j] = 0.f;

    float4 tA = *(const float4*)(Tb + (size_t)(c0 + ar) * HD + akq);
    float4 tB = *(const float4*)(Wo + (size_t)(o0 + ar) * HD + akq);

    for (int j0 = 0; j0 < HD; j0 += 16) {
        As[akq + 0][ar] = tA.x; As[akq + 1][ar] = tA.y;
        As[akq + 2][ar] = tA.z; As[akq + 3][ar] = tA.w;
        Bs[akq + 0][ar] = tB.x; Bs[akq + 1][ar] = tB.y;
        Bs[akq + 2][ar] = tB.z; Bs[akq + 3][ar] = tB.w;
        __syncthreads();
        if (j0 + 16 < HD) {
            tA = *(const float4*)(Tb + (size_t)(c0 + ar) * HD + j0 + 16 + akq);
            tB = *(const float4*)(Wo + (size_t)(o0 + ar) * HD + j0 + 16 + akq);
        }
        #pragma unroll
        for (int k = 0; k < 16; k++) {
            float4 a4 = *(const float4*)&As[k][ty * 4];
            float4 b4 = *(const float4*)&Bs[k][tx * 4];
            float aa[4] = {a4.x, a4.y, a4.z, a4.w};
            float bb[4] = {b4.x, b4.y, b4.z, b4.w};
            #pragma unroll
            for (int i = 0; i < 4; i++)
                #pragma unroll
                for (int j = 0; j < 4; j++)
                    acc[i][j] = fmaf(aa[i], bb[j], acc[i][j]);
        }
        __syncthreads();
    }

    #pragma unroll
    for (int i = 0; i < 4; i++)
        #pragma unroll
        for (int j = 0; j < 4; j++)
            g_F[((size_t)b * CC + c0 + ty * 4 + i) * OUTC + o0 + tx * 4 + j] = acc[i][j];
}

// ---------------------------------------------------------------------------
// k4_mma: out = U @ F + bo, tf32 mma.sync with cp.async 2-stage pipeline.
// ---------------------------------------------------------------------------
#define K4_ASTR (128 * 36)              // floats per A buffer
#define K4_BSTR (32 * 132)              // floats per B buffer
#define K4_SMEM ((2 * K4_ASTR + 2 * K4_BSTR) * 4)

__global__ __launch_bounds__(256) void k4_mma(const float* __restrict__ U,
                                              const float* __restrict__ bo,
                                              float* __restrict__ out) {
    extern __shared__ float sm4[];
    float* Asm = sm4;                    // 2 x [128][36]
    float* Bsm = sm4 + 2 * K4_ASTR;      // 2 x [32][132]
    const unsigned sbase = smem_u32(sm4);

    const int tid = threadIdx.x;
    const int wid = tid >> 5, lane = tid & 31;
    const int warp_m = wid & 3;
    const int warp_n = wid >> 2;
    const int gr = lane >> 2;
    const int tc = lane & 3;

    const int n0  = blockIdx.x * 128;
    const int mt0 = blockIdx.y * 128;
    const int b   = mt0 >> 14;
    const float* Fp = g_F + (size_t)b * CC * OUTC;

    float acc[2][8][4];
    #pragma unroll
    for (int mi = 0; mi < 2; mi++)
        #pragma unroll
        for (int ni = 0; ni < 8; ni++)
            #pragma unroll
            for (int q = 0; q < 4; q++) acc[mi][ni][q] = 0.f;

    const int am  = tid >> 3;            // 0..31 (+p*32)
    const int akq = (tid & 7) * 4;       // 0..28
    const int bk  = tid >> 5;            // 0..7  (+p*8)
    const int bnq = (tid & 31) * 4;      // 0..124

    auto issue = [&](int c, int buf) {
        const float* Ag = U + (size_t)mt0 * CC + c * 32;
        #pragma unroll
        for (int p = 0; p < 4; p++) {
            const int m = am + p * 32;
            unsigned dst = sbase + (unsigned)(buf * K4_ASTR + m * 36 + akq) * 4u;
            CP_ASYNC16(dst, Ag + (size_t)m * CC + akq);
        }
        const float* Bg = Fp + (size_t)(c * 32) * OUTC + n0;
        #pragma unroll
        for (int p = 0; p < 4; p++) {
            const int k = bk + p * 8;
            unsigned dst = sbase + (unsigned)(2 * K4_ASTR + buf * K4_BSTR + k * 132 + bnq) * 4u;
            CP_ASYNC16(dst, Bg + (size_t)k * OUTC + bnq);
        }
        CP_COMMIT();
    };

    issue(0, 0);

    for (int c = 0; c < 8; c++) {
        const int buf = c & 1;
        if (c < 7) { issue(c + 1, buf ^ 1); CP_WAIT1(); }
        else       { CP_WAIT0(); }
        __syncthreads();

        const float* Ab = Asm + buf * K4_ASTR;
        const float* Bb = Bsm + buf * K4_BSTR;

        #pragma unroll
        for (int ks = 0; ks < 4; ks++) {
            const int k8 = ks * 8;
            unsigned a[2][4];
            #pragma unroll
            for (int mi = 0; mi < 2; mi++) {
                const int mr = warp_m * 32 + mi * 16;
                a[mi][0] = to_tf32(Ab[(mr + gr) * 36 + k8 + tc]);
                a[mi][1] = to_tf32(Ab[(mr + gr + 8) * 36 + k8 + tc]);
                a[mi][2] = to_tf32(Ab[(mr + gr) * 36 + k8 + tc + 4]);
                a[mi][3] = to_tf32(Ab[(mr + gr + 8) * 36 + k8 + tc + 4]);
            }
            #pragma unroll
            for (int ni = 0; ni < 8; ni++) {
                const int nb = warp_n * 64 + ni * 8;
                unsigned b0 = to_tf32(Bb[(k8 + tc) * 132 + nb + gr]);
                unsigned b1 = to_tf32(Bb[(k8 + tc + 4) * 132 + nb + gr]);
                #pragma unroll
                for (int mi = 0; mi < 2; mi++)
                    MMA8(acc[mi][ni], a[mi][0], a[mi][1], a[mi][2], a[mi][3], b0, b1);
            }
        }
        __syncthreads();
    }

    #pragma unroll
    for (int mi = 0; mi < 2; mi++) {
        const int row = mt0 + warp_m * 32 + mi * 16 + gr;
        #pragma unroll
        for (int ni = 0; ni < 8; ni++) {
            const int col = n0 + warp_n * 64 + ni * 8 + tc * 2;
            const float2 bb = *(const float2*)(bo + col);
            float2 o0, o1;
            o0.x = acc[mi][ni][0] + bb.x;
            o0.y = acc[mi][ni][1] + bb.y;
            o1.x = acc[mi][ni][2] + bb.x;
            o1.y = acc[mi][ni][3] + bb.y;
            *(float2*)(out + (size_t)row * OUTC + col) = o0;
            *(float2*)(out + (size_t)(row + 8) * OUTC + col) = o1;
        }
    }
}

// ---------------------------------------------------------------------------
extern "C" void kernel_launch(void* const* d_in, const int* in_sizes, int n_in,
                              void* d_out, int out_size) {
    const float* u  = (const float*)d_in[0];
    // d_in[1] = pos_src -- unused by the reference computation
    const float* Wq = (const float*)d_in[2];
    const float* Wk = (const float*)d_in[3];
    const float* Wv = (const float*)d_in[4];
    const float* Wo = (const float*)d_in[5];
    const float* bo = (const float*)d_in[6];
    float* out = (float*)d_out;

    static int smem_set = 0;
    if (!smem_set) {
        cudaFuncSetAttribute(k4_mma, cudaFuncAttributeMaxDynamicSharedMemorySize, K4_SMEM);
        smem_set = 1;
    }

    k_g  <<<dim3(3, NCH, BB), 256>>>(u);
    kA   <<<dim3(CC, BB), 256>>>();
    kB1  <<<dim3(BB * HH, 2, 4), 256>>>(Wk, Wv);
    kB2T <<<BB * HH, 256>>>(Wk, Wv, Wq);
    k3c_F<<<dim3(4, 4, BB), 256>>>(Wo);
    k4_mma<<<dim3(2, 512), 256, K4_SMEM>>>(u, bo, out);
}

// round 13
// speedup vs baseline: 8.4099x; 1.2379x over previous
#include <cuda_runtime.h>
#include <cuda_fp16.h>
#include <cstdint>

#define BB 4
#define NN 16384
#define CC 256
#define HH 8
#define DD 64
#define HD 512
#define OUTC 256
#define NCH 32           // split-K chunks over the grid axis for G
#define KCH 512          // tokens per chunk

// static device scratch
__device__ float g_Gp[BB*NCH*CC*CC];     // per-chunk partials of G = U^T U
__device__ float g_sup[BB*NCH*CC];       // per-chunk column sums of U
__device__ float g_G[BB*CC*CC];          // reduced Gram matrices
__device__ float g_su[BB*CC];            // reduced column sums
__device__ float g_P[2*BB*HH*DD*CC];     // P[leg][bh] = W_h @ G   (64 x 256)
__device__ float g_T[BB*CC*HD];          // Wq_h^T @ kvhat, [b][c][h*64+e]
__device__ unsigned g_Fh2[BB*OUTC*(CC/2)]; // F^T as half2 c-pairs: [b][o][cpair]

__device__ __forceinline__ unsigned packh2(float lo, float hi) {
    __half2 h = __floats2half2_rn(lo, hi);   // .x (low bits) = lo = even index
    return *reinterpret_cast<unsigned*>(&h);
}
__device__ __forceinline__ float2 unpackh2(unsigned w) {
    __half2 h = *reinterpret_cast<__half2*>(&w);
    return __half22float2(h);
}

#define MMA16(accp, a0, a1, a2, a3, b0, b1) \
    asm volatile( \
        "mma.sync.aligned.m16n8k16.row.col.f32.f16.f16.f32 " \
        "{%0,%1,%2,%3}, {%4,%5,%6,%7}, {%8,%9}, {%0,%1,%2,%3};" \
        : "+f"((accp)[0]), "+f"((accp)[1]), "+f"((accp)[2]), "+f"((accp)[3]) \
        : "r"(a0), "r"(a1), "r"(a2), "r"(a3), "r"(b0), "r"(b1))

// ---------------------------------------------------------------------------
// k_g: split-K syrk partials via fp16 m16n8k16 mma (fp16 mantissa == tf32).
// grid (3 tiles, NCH, BB); tile -> quadrant (0,0),(0,1),(1,1).
// Us2[ch][tokpair] half2 words: the packed (even,odd) token pair IS the mma
// k-pair fragment, so every fragment register is a single LDS.32.
// ---------------------------------------------------------------------------
__global__ __launch_bounds__(256) void k_g(const float* __restrict__ U) {
    __shared__ unsigned Us2[256][9];        // [ch][tokpair 0..7], pad 9
    const int tile = blockIdx.x;            // 0..2
    const int ti = tile >> 1, tj = (tile + 1) >> 1;
    const int ch = blockIdx.y, b = blockIdx.z;
    const int tid = threadIdx.x;
    const int wid = tid >> 5, lane = tid & 31;
    const int warp_m = wid & 3, warp_n = wid >> 2;
    const int gr = lane >> 2, tc = lane & 3;
    const bool diag = (ti == tj);

    const float* Up = U + (size_t)(b * NN + ch * KCH) * CC;

    float acc[2][8][4];
    #pragma unroll
    for (int mi = 0; mi < 2; mi++)
        #pragma unroll
        for (int ni = 0; ni < 8; ni++)
            #pragma unroll
            for (int q = 0; q < 4; q++) acc[mi][ni][q] = 0.f;
    float s = 0.f;

    // loader: thread owns token-pair tp and 8 channels chb..chb+7
    const int tp  = tid & 7;
    const int chb = (tid >> 3) * 8;

    float4 v0a, v0b, v1a, v1b;
    {
        const float* r0 = Up + (size_t)(2 * tp) * CC + chb;
        const float* r1 = Up + (size_t)(2 * tp + 1) * CC + chb;
        v0a = *(const float4*)r0;       v0b = *(const float4*)(r0 + 4);
        v1a = *(const float4*)r1;       v1b = *(const float4*)(r1 + 4);
    }

    for (int t0 = 0; t0 < KCH; t0 += 16) {
        unsigned w[8];
        w[0] = packh2(v0a.x, v1a.x); w[1] = packh2(v0a.y, v1a.y);
        w[2] = packh2(v0a.z, v1a.z); w[3] = packh2(v0a.w, v1a.w);
        w[4] = packh2(v0b.x, v1b.x); w[5] = packh2(v0b.y, v1b.y);
        w[6] = packh2(v0b.z, v1b.z); w[7] = packh2(v0b.w, v1b.w);
        __syncthreads();
        #pragma unroll
        for (int i = 0; i < 8; i++) Us2[chb + i][tp] = w[i];
        __syncthreads();

        if (t0 + 16 < KCH) {
            const float* r0 = Up + (size_t)(t0 + 16 + 2 * tp) * CC + chb;
            const float* r1 = Up + (size_t)(t0 + 16 + 2 * tp + 1) * CC + chb;
            v0a = *(const float4*)r0;   v0b = *(const float4*)(r0 + 4);
            v1a = *(const float4*)r1;   v1b = *(const float4*)(r1 + 4);
        }

        if (tile == 1) {
            #pragma unroll
            for (int p = 0; p < 8; p++) {
                float2 f = unpackh2(Us2[tid][p]);
                s += f.x + f.y;
            }
        }

        unsigned a0[2], a1[2], a2[2], a3[2];
        #pragma unroll
        for (int mi = 0; mi < 2; mi++) {
            const int am = ti * 128 + warp_m * 16 + mi * 64;
            a0[mi] = Us2[am + gr][tc];
            a1[mi] = Us2[am + gr + 8][tc];
            a2[mi] = Us2[am + gr][tc + 4];
            a3[mi] = Us2[am + gr + 8][tc + 4];
        }
        #pragma unroll
        for (int ni = 0; ni < 8; ni++) {
            const int nb = warp_n * 8 + ni * 16;
            const int bn = tj * 128 + nb;
            unsigned b0 = Us2[bn + gr][tc];
            unsigned b1 = Us2[bn + gr][tc + 4];
            #pragma unroll
            for (int mi = 0; mi < 2; mi++) {
                const int mr = warp_m * 16 + mi * 64;
                if (diag && (nb + 8 <= mr)) continue;
                MMA16(acc[mi][ni], a0[mi], a1[mi], a2[mi], a3[mi], b0, b1);
            }
        }
    }

    float* op = g_Gp + (size_t)(b * NCH + ch) * CC * CC;
    #pragma unroll
    for (int mi = 0; mi < 2; mi++) {
        const int mr = warp_m * 16 + mi * 64;
        #pragma unroll
        for (int ni = 0; ni < 8; ni++) {
            const int nb = warp_n * 8 + ni * 16;
            if (diag && (nb + 8 <= mr)) continue;
            const int row = ti * 128 + mr + gr;
            const int col = tj * 128 + nb + tc * 2;
            float2 c0v = make_float2(acc[mi][ni][0], acc[mi][ni][1]);
            float2 c1v = make_float2(acc[mi][ni][2], acc[mi][ni][3]);
            *(float2*)(op + (size_t)row * CC + col) = c0v;
            *(float2*)(op + (size_t)(row + 8) * CC + col) = c1v;
        }
    }
    if (tile == 1) g_sup[(size_t)(b * NCH + ch) * CC + tid] = s;
}

// ---------------------------------------------------------------------------
// kA: reduce split-K partials -> g_G, g_su, reconstructing un-stored
// positions via symmetry (read the transposed, computed slot).
// ---------------------------------------------------------------------------
__global__ __launch_bounds__(256) void kA() {
    const int r = blockIdx.x, b = blockIdx.y, c = threadIdx.x;
    int rr = r, cc = c;
    const bool swap = ((r >= 128) && (c < 128)) ||
                      (((r >= 128) == (c >= 128)) && (c < r));
    if (swap) { rr = c; cc = r; }
    float s = 0.f;
    for (int ch = 0; ch < NCH; ch++)
        s += g_Gp[((size_t)(b * NCH + ch) * CC + rr) * CC + cc];
    g_G[((size_t)b * CC + r) * CC + c] = s;
    if (r == 0) {
        float t = 0.f;
        for (int ch = 0; ch < NCH; ch++)
            t += g_sup[(size_t)(b * NCH + ch) * CC + c];
        g_su[(size_t)b * CC + c] = t;
    }
}

// ---------------------------------------------------------------------------
// kB1: P[leg][b,h] = W_h @ G. grid (32 bh, 2 legs, 4 otiles) = 256 blocks.
// ---------------------------------------------------------------------------
__global__ __launch_bounds__(256) void kB1(const float* __restrict__ Wk,
                                           const float* __restrict__ Wv) {
    __shared__ float As[16][68];
    __shared__ float Bs[16][68];
    const int bh = blockIdx.x, leg = blockIdx.y, ot = blockIdx.z;
    const int b = bh >> 3, h = bh & 7;
    const float* W  = (leg ? Wv : Wk) + (size_t)h * DD * CC;
    const float* Gb = g_G + (size_t)b * CC * CC;
    const int o0 = ot * 64;
    const int tid = threadIdx.x;
    const int tx = tid & 15, ty = tid >> 4;

    const int ad = tid >> 2, akq = (tid & 3) * 4;
    const int bk = tid >> 4, bc4 = (tid & 15) * 4;

    float acc[4][4];
    #pragma unroll
    for (int i = 0; i < 4; i++)
        #pragma unroll
        for (int j = 0; j < 4; j++) acc[i][j] = 0.f;

    float4 wA = *(const float4*)(W + (size_t)ad * CC + akq);
    float4 wB = *(const float4*)(Gb + (size_t)bk * CC + o0 + bc4);

    for (int kt = 0; kt < CC; kt += 16) {
        As[akq + 0][ad] = wA.x; As[akq + 1][ad] = wA.y;
        As[akq + 2][ad] = wA.z; As[akq + 3][ad] = wA.w;
        *(float4*)&Bs[bk][bc4] = wB;
        __syncthreads();
        if (kt + 16 < CC) {
            wA = *(const float4*)(W + (size_t)ad * CC + kt + 16 + akq);
            wB = *(const float4*)(Gb + (size_t)(kt + 16 + bk) * CC + o0 + bc4);
        }
        #pragma unroll
        for (int k = 0; k < 16; k++) {
            float4 a4 = *(const float4*)&As[k][ty * 4];
            float4 b4 = *(const float4*)&Bs[k][tx * 4];
            float aa[4] = {a4.x, a4.y, a4.z, a4.w};
            float bb[4] = {b4.x, b4.y, b4.z, b4.w};
            #pragma unroll
            for (int i = 0; i < 4; i++)
                #pragma unroll
                for (int j = 0; j < 4; j++)
                    acc[i][j] = fmaf(aa[i], bb[j], acc[i][j]);
        }
        __syncthreads();
    }

    float* op = g_P + (size_t)(leg * BB * HH + bh) * DD * CC;
    #pragma unroll
    for (int i = 0; i < 4; i++)
        #pragma unroll
        for (int j = 0; j < 4; j++)
            op[(size_t)(ty * 4 + i) * CC + o0 + tx * 4 + j] = acc[i][j];
}

// ---------------------------------------------------------------------------
// kB2T: e-split version. grid (4 etiles, 32 bh). Each block: 64d x 16e kv
// tile + full mk/rk + its 16 mv/rv + the matching 16 T columns.
// ---------------------------------------------------------------------------
__global__ __launch_bounds__(256) void kB2T(const float* __restrict__ Wk,
                                            const float* __restrict__ Wv,
                                            const float* __restrict__ Wq) {
    __shared__ float As[16][68];
    __shared__ float Bs[16][20];
    __shared__ __align__(16) float sus[CC];
    __shared__ float mk[64], rk[64], mv[16], rv[16];
    __shared__ __align__(16) float kvs[64][16];
    const int et = blockIdx.x, e0 = et * 16;
    const int bh = blockIdx.y;
    const int b = bh >> 3, h = bh & 7;
    const int tid = threadIdx.x;
    const int tx = tid & 15, ty = tid >> 4;
    const float invN = 1.f / NN;

    const float* Pk  = g_P + (size_t)bh * DD * CC;
    const float* Pv  = g_P + (size_t)(BB * HH + bh) * DD * CC;
    const float* WkH = Wk + (size_t)h * DD * CC;
    const float* WvH = Wv + (size_t)h * DD * CC;

    sus[tid] = g_su[(size_t)b * CC + tid];

    const int ad = tid >> 2, akq = (tid & 3) * 4;

    float acc[4];
    #pragma unroll
    for (int i = 0; i < 4; i++) acc[i] = 0.f;

    float4 pA = *(const float4*)(Pk + (size_t)ad * CC + akq);
    float4 pB;
    if (tid < 64)
        pB = *(const float4*)(WvH + (size_t)(e0 + (tid >> 2)) * CC + akq);

    for (int kt = 0; kt < CC; kt += 16) {
        As[akq + 0][ad] = pA.x; As[akq + 1][ad] = pA.y;
        As[akq + 2][ad] = pA.z; As[akq + 3][ad] = pA.w;
        if (tid < 64) {
            const int e = tid >> 2;
            Bs[akq + 0][e] = pB.x; Bs[akq + 1][e] = pB.y;
            Bs[akq + 2][e] = pB.z; Bs[akq + 3][e] = pB.w;
        }
        __syncthreads();
        if (kt + 16 < CC) {
            pA = *(const float4*)(Pk + (size_t)ad * CC + kt + 16 + akq);
            if (tid < 64)
                pB = *(const float4*)(WvH + (size_t)(e0 + (tid >> 2)) * CC + kt + 16 + akq);
        }
        #pragma unroll
        for (int k = 0; k < 16; k++) {
            float4 a4 = *(const float4*)&As[k][ty * 4];
            float bb = Bs[k][tx];
            acc[0] = fmaf(a4.x, bb, acc[0]);
            acc[1] = fmaf(a4.y, bb, acc[1]);
            acc[2] = fmaf(a4.z, bb, acc[2]);
            acc[3] = fmaf(a4.w, bb, acc[3]);
        }
        __syncthreads();
    }

    if (tid < 64) {
        const int d = tid;
        float ss = 0.f, sm = 0.f;
        #pragma unroll 8
        for (int c = 0; c < CC; c += 4) {
            float4 p = *(const float4*)(Pk + (size_t)d * CC + c);
            float4 w = *(const float4*)(WkH + (size_t)d * CC + c);
            float4 s4 = *(const float4*)&sus[c];
            ss = fmaf(p.x, w.x, ss); ss = fmaf(p.y, w.y, ss);
            ss = fmaf(p.z, w.z, ss); ss = fmaf(p.w, w.w, ss);
            sm = fmaf(w.x, s4.x, sm); sm = fmaf(w.y, s4.y, sm);
            sm = fmaf(w.z, s4.z, sm); sm = fmaf(w.w, s4.w, sm);
        }
        const float m = sm * invN;
        mk[d] = m; rk[d] = rsqrtf(ss * invN - m * m + 1e-5f);
    } else if (tid < 80) {
        const int e = tid - 64;
        const int row = e0 + e;
        float ss = 0.f, sm = 0.f;
        #pragma unroll 8
        for (int c = 0; c < CC; c += 4) {
            float4 p = *(const float4*)(Pv + (size_t)row * CC + c);
            float4 w = *(const float4*)(WvH + (size_t)row * CC + c);
            float4 s4 = *(const float4*)&sus[c];
            ss = fmaf(p.x, w.x, ss); ss = fmaf(p.y, w.y, ss);
            ss = fmaf(p.z, w.z, ss); ss = fmaf(p.w, w.w, ss);
            sm = fmaf(w.x, s4.x, sm); sm = fmaf(w.y, s4.y, sm);
            sm = fmaf(w.z, s4.z, sm); sm = fmaf(w.w, s4.w, sm);
        }
        const float m = sm * invN;
        mv[e] = m; rv[e] = rsqrtf(ss * invN - m * m + 1e-5f);
    }
    __syncthreads();

    #pragma unroll
    for (int i = 0; i < 4; i++) {
        const int d = ty * 4 + i;
        kvs[d][tx] = rk[d] * rv[tx] * (acc[i] * invN - mk[d] * mv[tx]);
    }
    __syncthreads();

    // T columns for this e-range
    float accT[16];
    #pragma unroll
    for (int e = 0; e < 16; e++) accT[e] = 0.f;
    const int c = tid;
    #pragma unroll 8
    for (int d = 0; d < DD; d++) {
        const float wq = Wq[(size_t)(h * DD + d) * CC + c];
        #pragma unroll
        for (int e4 = 0; e4 < 4; e4++) {
            float4 t = *(const float4*)&kvs[d][e4 * 4];
            accT[e4*4+0] = fmaf(wq, t.x, accT[e4*4+0]);
            accT[e4*4+1] = fmaf(wq, t.y, accT[e4*4+1]);
            accT[e4*4+2] = fmaf(wq, t.z, accT[e4*4+2]);
            accT[e4*4+3] = fmaf(wq, t.w, accT[e4*4+3]);
        }
    }
    float* Tp = g_T + ((size_t)b * CC + c) * HD + h * DD + e0;
    #pragma unroll
    for (int e4 = 0; e4 < 4; e4++)
        *(float4*)(Tp + e4 * 4) = make_float4(accT[e4*4+0], accT[e4*4+1],
                                              accT[e4*4+2], accT[e4*4+3]);
}

// ---------------------------------------------------------------------------
// k3c_F: F = T @ Wo^T, stored transposed + c-pair half2-packed into g_Fh2.
// ---------------------------------------------------------------------------
__global__ __launch_bounds__(256) void k3c_F(const float* __restrict__ Wo) {
    __shared__ float As[16][68];
    __shared__ float Bs[16][68];
    const int o0 = blockIdx.x * 64;
    const int c0 = blockIdx.y * 64;
    const int b  = blockIdx.z;
    const int tid = threadIdx.x;
    const int tx = tid & 15, ty = tid >> 4;
    const int ar = tid >> 2, akq = (tid & 3) * 4;

    const float* Tb = g_T + (size_t)b * CC * HD;

    float acc[4][4];
    #pragma unroll
    for (int i = 0; i < 4; i++)
        #pragma unroll
        for (int j = 0; j < 4; j++) acc[i][j] = 0.f;

    float4 tA = *(const float4*)(Tb + (size_t)(c0 + ar) * HD + akq);
    float4 tB = *(const float4*)(Wo + (size_t)(o0 + ar) * HD + akq);

    for (int j0 = 0; j0 < HD; j0 += 16) {
        As[akq + 0][ar] = tA.x; As[akq + 1][ar] = tA.y;
        As[akq + 2][ar] = tA.z; As[akq + 3][ar] = tA.w;
        Bs[akq + 0][ar] = tB.x; Bs[akq + 1][ar] = tB.y;
        Bs[akq + 2][ar] = tB.z; Bs[akq + 3][ar] = tB.w;
        __syncthreads();
        if (j0 + 16 < HD) {
            tA = *(const float4*)(Tb + (size_t)(c0 + ar) * HD + j0 + 16 + akq);
            tB = *(const float4*)(Wo + (size_t)(o0 + ar) * HD + j0 + 16 + akq);
        }
        #pragma unroll
        for (int k = 0; k < 16; k++) {
            float4 a4 = *(const float4*)&As[k][ty * 4];
            float4 b4 = *(const float4*)&Bs[k][tx * 4];
            float aa[4] = {a4.x, a4.y, a4.z, a4.w};
            float bb[4] = {b4.x, b4.y, b4.z, b4.w};
            #pragma unroll
            for (int i = 0; i < 4; i++)
                #pragma unroll
                for (int j = 0; j < 4; j++)
                    acc[i][j] = fmaf(aa[i], bb[j], acc[i][j]);
        }
        __syncthreads();
    }

    const int cw0 = (c0 + ty * 4) >> 1;   // c-pair index
    #pragma unroll
    for (int j = 0; j < 4; j++) {
        const int o = o0 + tx * 4 + j;
        unsigned* Fr = g_Fh2 + ((size_t)(b * OUTC + o) << 7);
        Fr[cw0]     = packh2(acc[0][j], acc[1][j]);
        Fr[cw0 + 1] = packh2(acc[2][j], acc[3][j]);
    }
}

// ---------------------------------------------------------------------------
// k4_mma: out = U @ F + bo via fp16 m16n8k16. A packed to half2 k-pairs at
// store; B read pre-packed from g_Fh2. CTA 128x128, warp 32x64.
// Row stride 20 words: uint4 stores stay 16B-aligned AND fragment loads
// remain bank-conflict-free (20*gr mod 32 spans 8 distinct multiples of 4).
// ---------------------------------------------------------------------------
__global__ __launch_bounds__(256) void k4_mma(const float* __restrict__ U,
                                              const float* __restrict__ bo,
                                              float* __restrict__ out) {
    __shared__ unsigned As2[128][20];   // [m][kpair 0..15], pad 20 (16B-aligned rows)
    __shared__ unsigned Bs2[128][20];   // [n][kpair 0..15]

    const int tid = threadIdx.x;
    const int wid = tid >> 5, lane = tid & 31;
    const int warp_m = wid & 3;
    const int warp_n = wid >> 2;
    const int gr = lane >> 2;
    const int tc = lane & 3;

    const int n0  = blockIdx.x * 128;
    const int mt0 = blockIdx.y * 128;
    const int b   = mt0 >> 14;

    float acc[2][8][4];
    #pragma unroll
    for (int mi = 0; mi < 2; mi++)
        #pragma unroll
        for (int ni = 0; ni < 8; ni++)
            #pragma unroll
            for (int q = 0; q < 4; q++) acc[mi][ni][q] = 0.f;

    const int row = tid >> 1;            // 0..127 (m for A, n-offset for B)
    const int kh2 = (tid & 1) * 8;       // word offset within 16-word chunk

    const float* Ag0 = U + (size_t)(mt0 + row) * CC + kh2 * 2;
    const unsigned* Bg0 = g_Fh2 + ((size_t)(b * OUTC + n0 + row) << 7) + kh2;

    float4 fa[4];
    uint4 fb[2];
    #pragma unroll
    for (int q = 0; q < 4; q++) fa[q] = *(const float4*)(Ag0 + q * 4);
    fb[0] = *(const uint4*)Bg0;
    fb[1] = *(const uint4*)(Bg0 + 4);

    for (int c = 0; c < 8; c++) {
        uint4 aw0, aw1;
        aw0.x = packh2(fa[0].x, fa[0].y); aw0.y = packh2(fa[0].z, fa[0].w);
        aw0.z = packh2(fa[1].x, fa[1].y); aw0.w = packh2(fa[1].z, fa[1].w);
        aw1.x = packh2(fa[2].x, fa[2].y); aw1.y = packh2(fa[2].z, fa[2].w);
        aw1.z = packh2(fa[3].x, fa[3].y); aw1.w = packh2(fa[3].z, fa[3].w);
        __syncthreads();
        *(uint4*)&As2[row][kh2]     = aw0;
        *(uint4*)&As2[row][kh2 + 4] = aw1;
        *(uint4*)&Bs2[row][kh2]     = fb[0];
        *(uint4*)&Bs2[row][kh2 + 4] = fb[1];
        __syncthreads();

        if (c < 7) {
            const float* Ag = Ag0 + (c + 1) * 32;
            #pragma unroll
            for (int q = 0; q < 4; q++) fa[q] = *(const float4*)(Ag + q * 4);
            const unsigned* Bg = Bg0 + (c + 1) * 16;
            fb[0] = *(const uint4*)Bg;
            fb[1] = *(const uint4*)(Bg + 4);
        }

        #pragma unroll
        for (int ks = 0; ks < 2; ks++) {
            const int kb = ks * 8;
            unsigned a0[2], a1[2], a2[2], a3[2];
            #pragma unroll
            for (int mi = 0; mi < 2; mi++) {
                const int mr = warp_m * 32 + mi * 16;
                a0[mi] = As2[mr + gr][kb + tc];
                a1[mi] = As2[mr + gr + 8][kb + tc];
                a2[mi] = As2[mr + gr][kb + tc + 4];
                a3[mi] = As2[mr + gr + 8][kb + tc + 4];
            }
            #pragma unroll
            for (int ni = 0; ni < 8; ni++) {
                const int nb = warp_n * 64 + ni * 8;
                unsigned b0 = Bs2[nb + gr][kb + tc];
                unsigned b1 = Bs2[nb + gr][kb + tc + 4];
                #pragma unroll
                for (int mi = 0; mi < 2; mi++)
                    MMA16(acc[mi][ni], a0[mi], a1[mi], a2[mi], a3[mi], b0, b1);
            }
        }
    }

    #pragma unroll
    for (int mi = 0; mi < 2; mi++) {
        const int orow = mt0 + warp_m * 32 + mi * 16 + gr;
        #pragma unroll
        for (int ni = 0; ni < 8; ni++) {
            const int col = n0 + warp_n * 64 + ni * 8 + tc * 2;
            const float2 bb = *(const float2*)(bo + col);
            float2 o0v, o1v;
            o0v.x = acc[mi][ni][0] + bb.x;
            o0v.y = acc[mi][ni][1] + bb.y;
            o1v.x = acc[mi][ni][2] + bb.x;
            o1v.y = acc[mi][ni][3] + bb.y;
            *(float2*)(out + (size_t)orow * OUTC + col) = o0v;
            *(float2*)(out + (size_t)(orow + 8) * OUTC + col) = o1v;
        }
    }
}

// ---------------------------------------------------------------------------
extern "C" void kernel_launch(void* const* d_in, const int* in_sizes, int n_in,
                              void* d_out, int out_size) {
    const float* u  = (const float*)d_in[0];
    // d_in[1] = pos_src -- unused by the reference computation
    const float* Wq = (const float*)d_in[2];
    const float* Wk = (const float*)d_in[3];
    const float* Wv = (const float*)d_in[4];
    const float* Wo = (const float*)d_in[5];
    const float* bo = (const float*)d_in[6];
    float* out = (float*)d_out;

    k_g  <<<dim3(3, NCH, BB), 256>>>(u);
    kA   <<<dim3(CC, BB), 256>>>();
    kB1  <<<dim3(BB * HH, 2, 4), 256>>>(Wk, Wv);
    kB2T <<<dim3(4, BB * HH), 256>>>(Wk, Wv, Wq);
    k3c_F<<<dim3(4, 4, BB), 256>>>(Wo);
    k4_mma<<<dim3(2, 512), 256>>>(u, bo, out);
}

// round 14
// speedup vs baseline: 9.0023x; 1.0704x over previous
#include <cuda_runtime.h>
#include <cuda_fp16.h>
#include <cstdint>

#define BB 4
#define NN 16384
#define CC 256
#define HH 8
#define DD 64
#define HD 512
#define OUTC 256
#define NCH 32           // split-K chunks over the grid axis for G
#define KCH 512          // tokens per chunk

// static device scratch
__device__ float g_Gp[BB*NCH*CC*CC];     // per-chunk partials of G = U^T U
__device__ float g_sup[BB*NCH*CC];       // per-chunk column sums of U
__device__ float g_G[BB*CC*CC];          // reduced Gram matrices
__device__ float g_su[BB*CC];            // reduced column sums
__device__ float g_P[2*BB*HH*DD*CC];     // P[leg][bh] = W_h @ G   (64 x 256)
__device__ float g_ssp[2*BB*HH*4*DD];    // per-otile partials of diag(P W^T)
__device__ float g_smp[2*BB*HH*4*DD];    // per-otile partials of W @ su
__device__ float g_T[BB*CC*HD];          // Wq_h^T @ kvhat, [b][c][h*64+e]
__device__ unsigned g_Fh2[BB*OUTC*(CC/2)]; // F^T as half2 c-pairs: [b][o][cpair]

__device__ __forceinline__ unsigned packh2(float lo, float hi) {
    __half2 h = __floats2half2_rn(lo, hi);   // .x (low bits) = lo = even index
    return *reinterpret_cast<unsigned*>(&h);
}
__device__ __forceinline__ float2 unpackh2(unsigned w) {
    __half2 h = *reinterpret_cast<__half2*>(&w);
    return __half22float2(h);
}

#define MMA16(accp, a0, a1, a2, a3, b0, b1) \
    asm volatile( \
        "mma.sync.aligned.m16n8k16.row.col.f32.f16.f16.f32 " \
        "{%0,%1,%2,%3}, {%4,%5,%6,%7}, {%8,%9}, {%0,%1,%2,%3};" \
        : "+f"((accp)[0]), "+f"((accp)[1]), "+f"((accp)[2]), "+f"((accp)[3]) \
        : "r"(a0), "r"(a1), "r"(a2), "r"(a3), "r"(b0), "r"(b1))

// ---------------------------------------------------------------------------
// k_g: split-K syrk partials via fp16 m16n8k16 mma (fp16 mantissa == tf32).
// grid (3 tiles, NCH, BB); tile -> quadrant (0,0),(0,1),(1,1).
// ---------------------------------------------------------------------------
__global__ __launch_bounds__(256) void k_g(const float* __restrict__ U) {
    __shared__ unsigned Us2[256][9];        // [ch][tokpair 0..7], pad 9
    const int tile = blockIdx.x;            // 0..2
    const int ti = tile >> 1, tj = (tile + 1) >> 1;
    const int ch = blockIdx.y, b = blockIdx.z;
    const int tid = threadIdx.x;
    const int wid = tid >> 5, lane = tid & 31;
    const int warp_m = wid & 3, warp_n = wid >> 2;
    const int gr = lane >> 2, tc = lane & 3;
    const bool diag = (ti == tj);

    const float* Up = U + (size_t)(b * NN + ch * KCH) * CC;

    float acc[2][8][4];
    #pragma unroll
    for (int mi = 0; mi < 2; mi++)
        #pragma unroll
        for (int ni = 0; ni < 8; ni++)
            #pragma unroll
            for (int q = 0; q < 4; q++) acc[mi][ni][q] = 0.f;
    float s = 0.f;

    const int tp  = tid & 7;
    const int chb = (tid >> 3) * 8;

    float4 v0a, v0b, v1a, v1b;
    {
        const float* r0 = Up + (size_t)(2 * tp) * CC + chb;
        const float* r1 = Up + (size_t)(2 * tp + 1) * CC + chb;
        v0a = *(const float4*)r0;       v0b = *(const float4*)(r0 + 4);
        v1a = *(const float4*)r1;       v1b = *(const float4*)(r1 + 4);
    }

    for (int t0 = 0; t0 < KCH; t0 += 16) {
        unsigned w[8];
        w[0] = packh2(v0a.x, v1a.x); w[1] = packh2(v0a.y, v1a.y);
        w[2] = packh2(v0a.z, v1a.z); w[3] = packh2(v0a.w, v1a.w);
        w[4] = packh2(v0b.x, v1b.x); w[5] = packh2(v0b.y, v1b.y);
        w[6] = packh2(v0b.z, v1b.z); w[7] = packh2(v0b.w, v1b.w);
        __syncthreads();
        #pragma unroll
        for (int i = 0; i < 8; i++) Us2[chb + i][tp] = w[i];
        __syncthreads();

        if (t0 + 16 < KCH) {
            const float* r0 = Up + (size_t)(t0 + 16 + 2 * tp) * CC + chb;
            const float* r1 = Up + (size_t)(t0 + 16 + 2 * tp + 1) * CC + chb;
            v0a = *(const float4*)r0;   v0b = *(const float4*)(r0 + 4);
            v1a = *(const float4*)r1;   v1b = *(const float4*)(r1 + 4);
        }

        if (tile == 1) {
            #pragma unroll
            for (int p = 0; p < 8; p++) {
                float2 f = unpackh2(Us2[tid][p]);
                s += f.x + f.y;
            }
        }

        unsigned a0[2], a1[2], a2[2], a3[2];
        #pragma unroll
        for (int mi = 0; mi < 2; mi++) {
            const int am = ti * 128 + warp_m * 16 + mi * 64;
            a0[mi] = Us2[am + gr][tc];
            a1[mi] = Us2[am + gr + 8][tc];
            a2[mi] = Us2[am + gr][tc + 4];
            a3[mi] = Us2[am + gr + 8][tc + 4];
        }
        #pragma unroll
        for (int ni = 0; ni < 8; ni++) {
            const int nb = warp_n * 8 + ni * 16;
            const int bn = tj * 128 + nb;
            unsigned b0 = Us2[bn + gr][tc];
            unsigned b1 = Us2[bn + gr][tc + 4];
            #pragma unroll
            for (int mi = 0; mi < 2; mi++) {
                const int mr = warp_m * 16 + mi * 64;
                if (diag && (nb + 8 <= mr)) continue;
                MMA16(acc[mi][ni], a0[mi], a1[mi], a2[mi], a3[mi], b0, b1);
            }
        }
    }

    float* op = g_Gp + (size_t)(b * NCH + ch) * CC * CC;
    #pragma unroll
    for (int mi = 0; mi < 2; mi++) {
        const int mr = warp_m * 16 + mi * 64;
        #pragma unroll
        for (int ni = 0; ni < 8; ni++) {
            const int nb = warp_n * 8 + ni * 16;
            if (diag && (nb + 8 <= mr)) continue;
            const int row = ti * 128 + mr + gr;
            const int col = tj * 128 + nb + tc * 2;
            float2 c0v = make_float2(acc[mi][ni][0], acc[mi][ni][1]);
            float2 c1v = make_float2(acc[mi][ni][2], acc[mi][ni][3]);
            *(float2*)(op + (size_t)row * CC + col) = c0v;
            *(float2*)(op + (size_t)(row + 8) * CC + col) = c1v;
        }
    }
    if (tile == 1) g_sup[(size_t)(b * NCH + ch) * CC + tid] = s;
}

// ---------------------------------------------------------------------------
// kA: reduce split-K partials -> g_G, g_su (symmetry reconstruct).
// ---------------------------------------------------------------------------
__global__ __launch_bounds__(256) void kA() {
    const int r = blockIdx.x, b = blockIdx.y, c = threadIdx.x;
    int rr = r, cc = c;
    const bool swap = ((r >= 128) && (c < 128)) ||
                      (((r >= 128) == (c >= 128)) && (c < r));
    if (swap) { rr = c; cc = r; }
    float s = 0.f;
    for (int ch = 0; ch < NCH; ch++)
        s += g_Gp[((size_t)(b * NCH + ch) * CC + rr) * CC + cc];
    g_G[((size_t)b * CC + r) * CC + c] = s;
    if (r == 0) {
        float t = 0.f;
        for (int ch = 0; ch < NCH; ch++)
            t += g_sup[(size_t)(b * NCH + ch) * CC + c];
        g_su[(size_t)b * CC + c] = t;
    }
}

// ---------------------------------------------------------------------------
// kB1: P[leg][b,h] = W_h @ G. grid (32 bh, 2 legs, 4 otiles) = 256 blocks.
// Epilogue emits per-otile stat partials: ss_d = sum_o P[d][o] W[d][o],
// sm_d = sum_o W[d][o] su[o]  (exactly the dots kB2T used to redo 4x).
// ---------------------------------------------------------------------------
__global__ __launch_bounds__(256) void kB1(const float* __restrict__ Wk,
                                           const float* __restrict__ Wv) {
    __shared__ float SB[2][16][68];
    float (*As)[68] = SB[0];
    float (*Bs)[68] = SB[1];
    const int bh = blockIdx.x, leg = blockIdx.y, ot = blockIdx.z;
    const int b = bh >> 3, h = bh & 7;
    const float* W  = (leg ? Wv : Wk) + (size_t)h * DD * CC;
    const float* Gb = g_G + (size_t)b * CC * CC;
    const int o0 = ot * 64;
    const int tid = threadIdx.x;
    const int tx = tid & 15, ty = tid >> 4;

    const int ad = tid >> 2, akq = (tid & 3) * 4;
    const int bk = tid >> 4, bc4 = (tid & 15) * 4;

    float acc[4][4];
    #pragma unroll
    for (int i = 0; i < 4; i++)
        #pragma unroll
        for (int j = 0; j < 4; j++) acc[i][j] = 0.f;

    float4 wA = *(const float4*)(W + (size_t)ad * CC + akq);
    float4 wB = *(const float4*)(Gb + (size_t)bk * CC + o0 + bc4);

    for (int kt = 0; kt < CC; kt += 16) {
        As[akq + 0][ad] = wA.x; As[akq + 1][ad] = wA.y;
        As[akq + 2][ad] = wA.z; As[akq + 3][ad] = wA.w;
        *(float4*)&Bs[bk][bc4] = wB;
        __syncthreads();
        if (kt + 16 < CC) {
            wA = *(const float4*)(W + (size_t)ad * CC + kt + 16 + akq);
            wB = *(const float4*)(Gb + (size_t)(kt + 16 + bk) * CC + o0 + bc4);
        }
        #pragma unroll
        for (int k = 0; k < 16; k++) {
            float4 a4 = *(const float4*)&As[k][ty * 4];
            float4 b4 = *(const float4*)&Bs[k][tx * 4];
            float aa[4] = {a4.x, a4.y, a4.z, a4.w};
            float bb[4] = {b4.x, b4.y, b4.z, b4.w};
            #pragma unroll
            for (int i = 0; i < 4; i++)
                #pragma unroll
                for (int j = 0; j < 4; j++)
                    acc[i][j] = fmaf(aa[i], bb[j], acc[i][j]);
        }
        __syncthreads();
    }

    float* op = g_P + (size_t)(leg * BB * HH + bh) * DD * CC;
    const float4 su4 = *(const float4*)(g_su + (size_t)b * CC + o0 + tx * 4);
    float* red_ss = &SB[0][0][0];     // reuse smem: 64 x 16
    float* red_sm = &SB[1][0][0];
    #pragma unroll
    for (int i = 0; i < 4; i++) {
        const int d = ty * 4 + i;
        #pragma unroll
        for (int j = 0; j < 4; j++)
            op[(size_t)d * CC + o0 + tx * 4 + j] = acc[i][j];
        float4 w4 = *(const float4*)(W + (size_t)d * CC + o0 + tx * 4);
        float ssp = acc[i][0] * w4.x + acc[i][1] * w4.y
                  + acc[i][2] * w4.z + acc[i][3] * w4.w;
        float smp = w4.x * su4.x + w4.y * su4.y + w4.z * su4.z + w4.w * su4.w;
        red_ss[d * 16 + tx] = ssp;
        red_sm[d * 16 + tx] = smp;
    }
    __syncthreads();
    if (tid < 64) {
        float ss = 0.f, sm = 0.f;
        #pragma unroll
        for (int t = 0; t < 16; t++) {
            ss += red_ss[tid * 16 + t];
            sm += red_sm[tid * 16 + t];
        }
        const size_t idx = (size_t)((leg * BB * HH + bh) * 4 + ot) * DD + tid;
        g_ssp[idx] = ss;
        g_smp[idx] = sm;
    }
}

// ---------------------------------------------------------------------------
// kB2T: e-split. grid (4 etiles, 32 bh). Stats now read pre-reduced
// partials from kB1 (4 adds) instead of 256-length global dots.
// ---------------------------------------------------------------------------
__global__ __launch_bounds__(256) void kB2T(const float* __restrict__ Wv,
                                            const float* __restrict__ Wq) {
    __shared__ float As[16][68];
    __shared__ float Bs[16][20];
    __shared__ float mk[64], rk[64], mv[16], rv[16];
    __shared__ __align__(16) float kvs[64][16];
    const int et = blockIdx.x, e0 = et * 16;
    const int bh = blockIdx.y;
    const int b = bh >> 3, h = bh & 7;
    const int tid = threadIdx.x;
    const int tx = tid & 15, ty = tid >> 4;
    const float invN = 1.f / NN;

    const float* Pk  = g_P + (size_t)bh * DD * CC;
    const float* WvH = Wv + (size_t)h * DD * CC;

    const int ad = tid >> 2, akq = (tid & 3) * 4;

    float acc[4];
    #pragma unroll
    for (int i = 0; i < 4; i++) acc[i] = 0.f;

    float4 pA = *(const float4*)(Pk + (size_t)ad * CC + akq);
    float4 pB;
    if (tid < 64)
        pB = *(const float4*)(WvH + (size_t)(e0 + (tid >> 2)) * CC + akq);

    // stats from partials (overlaps the GEMM loads)
    if (tid < 64) {
        const int d = tid;
        const float* sp = g_ssp + (size_t)bh * 4 * DD + d;
        const float* mp = g_smp + (size_t)bh * 4 * DD + d;
        float ss = sp[0] + sp[64] + sp[128] + sp[192];
        float sm = mp[0] + mp[64] + mp[128] + mp[192];
        const float m = sm * invN;
        mk[d] = m; rk[d] = rsqrtf(ss * invN - m * m + 1e-5f);
    } else if (tid < 80) {
        const int e = tid - 64;
        const int row = e0 + e;
        const float* sp = g_ssp + (size_t)(BB * HH + bh) * 4 * DD + row;
        const float* mp = g_smp + (size_t)(BB * HH + bh) * 4 * DD + row;
        float ss = sp[0] + sp[64] + sp[128] + sp[192];
        float sm = mp[0] + mp[64] + mp[128] + mp[192];
        const float m = sm * invN;
        mv[e] = m; rv[e] = rsqrtf(ss * invN - m * m + 1e-5f);
    }

    for (int kt = 0; kt < CC; kt += 16) {
        As[akq + 0][ad] = pA.x; As[akq + 1][ad] = pA.y;
        As[akq + 2][ad] = pA.z; As[akq + 3][ad] = pA.w;
        if (tid < 64) {
            const int e = tid >> 2;
            Bs[akq + 0][e] = pB.x; Bs[akq + 1][e] = pB.y;
            Bs[akq + 2][e] = pB.z; Bs[akq + 3][e] = pB.w;
        }
        __syncthreads();
        if (kt + 16 < CC) {
            pA = *(const float4*)(Pk + (size_t)ad * CC + kt + 16 + akq);
            if (tid < 64)
                pB = *(const float4*)(WvH + (size_t)(e0 + (tid >> 2)) * CC + kt + 16 + akq);
        }
        #pragma unroll
        for (int k = 0; k < 16; k++) {
            float4 a4 = *(const float4*)&As[k][ty * 4];
            float bb = Bs[k][tx];
            acc[0] = fmaf(a4.x, bb, acc[0]);
            acc[1] = fmaf(a4.y, bb, acc[1]);
            acc[2] = fmaf(a4.z, bb, acc[2]);
            acc[3] = fmaf(a4.w, bb, acc[3]);
        }
        __syncthreads();
    }

    #pragma unroll
    for (int i = 0; i < 4; i++) {
        const int d = ty * 4 + i;
        kvs[d][tx] = rk[d] * rv[tx] * (acc[i] * invN - mk[d] * mv[tx]);
    }
    __syncthreads();

    float accT[16];
    #pragma unroll
    for (int e = 0; e < 16; e++) accT[e] = 0.f;
    const int c = tid;
    #pragma unroll 8
    for (int d = 0; d < DD; d++) {
        const float wq = Wq[(size_t)(h * DD + d) * CC + c];
        #pragma unroll
        for (int e4 = 0; e4 < 4; e4++) {
            float4 t = *(const float4*)&kvs[d][e4 * 4];
            accT[e4*4+0] = fmaf(wq, t.x, accT[e4*4+0]);
            accT[e4*4+1] = fmaf(wq, t.y, accT[e4*4+1]);
            accT[e4*4+2] = fmaf(wq, t.z, accT[e4*4+2]);
            accT[e4*4+3] = fmaf(wq, t.w, accT[e4*4+3]);
        }
    }
    float* Tp = g_T + ((size_t)b * CC + c) * HD + h * DD + e0;
    #pragma unroll
    for (int e4 = 0; e4 < 4; e4++)
        *(float4*)(Tp + e4 * 4) = make_float4(accT[e4*4+0], accT[e4*4+1],
                                              accT[e4*4+2], accT[e4*4+3]);
}

// ---------------------------------------------------------------------------
// k3c_F: F = T @ Wo^T, stored transposed + c-pair half2-packed into g_Fh2.
// ---------------------------------------------------------------------------
__global__ __launch_bounds__(256) void k3c_F(const float* __restrict__ Wo) {
    __shared__ float As[16][68];
    __shared__ float Bs[16][68];
    const int o0 = blockIdx.x * 64;
    const int c0 = blockIdx.y * 64;
    const int b  = blockIdx.z;
    const int tid = threadIdx.x;
    const int tx = tid & 15, ty = tid >> 4;
    const int ar = tid >> 2, akq = (tid & 3) * 4;

    const float* Tb = g_T + (size_t)b * CC * HD;

    float acc[4][4];
    #pragma unroll
    for (int i = 0; i < 4; i++)
        #pragma unroll
        for (int j = 0; j < 4; j++) acc[i][j] = 0.f;

    float4 tA = *(const float4*)(Tb + (size_t)(c0 + ar) * HD + akq);
    float4 tB = *(const float4*)(Wo + (size_t)(o0 + ar) * HD + akq);

    for (int j0 = 0; j0 < HD; j0 += 16) {
        As[akq + 0][ar] = tA.x; As[akq + 1][ar] = tA.y;
        As[akq + 2][ar] = tA.z; As[akq + 3][ar] = tA.w;
        Bs[akq + 0][ar] = tB.x; Bs[akq + 1][ar] = tB.y;
        Bs[akq + 2][ar] = tB.z; Bs[akq + 3][ar] = tB.w;
        __syncthreads();
        if (j0 + 16 < HD) {
            tA = *(const float4*)(Tb + (size_t)(c0 + ar) * HD + j0 + 16 + akq);
            tB = *(const float4*)(Wo + (size_t)(o0 + ar) * HD + j0 + 16 + akq);
        }
        #pragma unroll
        for (int k = 0; k < 16; k++) {
            float4 a4 = *(const float4*)&As[k][ty * 4];
            float4 b4 = *(const float4*)&Bs[k][tx * 4];
            float aa[4] = {a4.x, a4.y, a4.z, a4.w};
            float bb[4] = {b4.x, b4.y, b4.z, b4.w};
            #pragma unroll
            for (int i = 0; i < 4; i++)
                #pragma unroll
                for (int j = 0; j < 4; j++)
                    acc[i][j] = fmaf(aa[i], bb[j], acc[i][j]);
        }
        __syncthreads();
    }

    const int cw0 = (c0 + ty * 4) >> 1;   // c-pair index
    #pragma unroll
    for (int j = 0; j < 4; j++) {
        const int o = o0 + tx * 4 + j;
        unsigned* Fr = g_Fh2 + ((size_t)(b * OUTC + o) << 7);
        Fr[cw0]     = packh2(acc[0][j], acc[1][j]);
        Fr[cw0 + 1] = packh2(acc[2][j], acc[3][j]);
    }
}

// ---------------------------------------------------------------------------
// k4_mma: out = U @ F + bo via fp16 m16n8k16, single n-pass (CTA 128x256).
// 512 threads, 4x4 warp grid, warp tile 32x64. U read exactly once.
// ---------------------------------------------------------------------------
__global__ __launch_bounds__(512) void k4_mma(const float* __restrict__ U,
                                              const float* __restrict__ bo,
                                              float* __restrict__ out) {
    __shared__ unsigned As2[128][20];   // [m][kpair 0..15], pad 20
    __shared__ unsigned Bs2[256][20];   // [n][kpair 0..15]

    const int tid = threadIdx.x;
    const int wid = tid >> 5, lane = tid & 31;
    const int warp_m = wid & 3;
    const int warp_n = wid >> 2;        // 0..3
    const int gr = lane >> 2;
    const int tc = lane & 3;

    const int mt0 = blockIdx.x * 128;
    const int b   = mt0 >> 14;

    float acc[2][8][4];
    #pragma unroll
    for (int mi = 0; mi < 2; mi++)
        #pragma unroll
        for (int ni = 0; ni < 8; ni++)
            #pragma unroll
            for (int q = 0; q < 4; q++) acc[mi][ni][q] = 0.f;

    const int arow = tid >> 2;           // 0..127
    const int akw  = (tid & 3) * 4;      // word offset 0,4,8,12
    const int brow = tid >> 1;           // 0..255
    const int bkw  = (tid & 1) * 8;

    const float* Ag0 = U + (size_t)(mt0 + arow) * CC + akw * 2;
    const unsigned* Bg0 = g_Fh2 + ((size_t)(b * OUTC + brow) << 7) + bkw;

    float4 fa[2];
    uint4 fb[2];
    fa[0] = *(const float4*)Ag0;
    fa[1] = *(const float4*)(Ag0 + 4);
    fb[0] = *(const uint4*)Bg0;
    fb[1] = *(const uint4*)(Bg0 + 4);

    for (int c = 0; c < 8; c++) {
        uint4 aw;
        aw.x = packh2(fa[0].x, fa[0].y); aw.y = packh2(fa[0].z, fa[0].w);
        aw.z = packh2(fa[1].x, fa[1].y); aw.w = packh2(fa[1].z, fa[1].w);
        __syncthreads();
        *(uint4*)&As2[arow][akw]     = aw;
        *(uint4*)&Bs2[brow][bkw]     = fb[0];
        *(uint4*)&Bs2[brow][bkw + 4] = fb[1];
        __syncthreads();

        if (c < 7) {
            const float* Ag = Ag0 + (c + 1) * 32;
            fa[0] = *(const float4*)Ag;
            fa[1] = *(const float4*)(Ag + 4);
            const unsigned* Bg = Bg0 + (c + 1) * 16;
            fb[0] = *(const uint4*)Bg;
            fb[1] = *(const uint4*)(Bg + 4);
        }

        #pragma unroll
        for (int ks = 0; ks < 2; ks++) {
            const int kb = ks * 8;
            unsigned a0[2], a1[2], a2[2], a3[2];
            #pragma unroll
            for (int mi = 0; mi < 2; mi++) {
                const int mr = warp_m * 32 + mi * 16;
                a0[mi] = As2[mr + gr][kb + tc];
                a1[mi] = As2[mr + gr + 8][kb + tc];
                a2[mi] = As2[mr + gr][kb + tc + 4];
                a3[mi] = As2[mr + gr + 8][kb + tc + 4];
            }
            #pragma unroll
            for (int ni = 0; ni < 8; ni++) {
                const int nb = warp_n * 64 + ni * 8;
                unsigned b0 = Bs2[nb + gr][kb + tc];
                unsigned b1 = Bs2[nb + gr][kb + tc + 4];
                #pragma unroll
                for (int mi = 0; mi < 2; mi++)
                    MMA16(acc[mi][ni], a0[mi], a1[mi], a2[mi], a3[mi], b0, b1);
            }
        }
    }

    #pragma unroll
    for (int mi = 0; mi < 2; mi++) {
        const int orow = mt0 + warp_m * 32 + mi * 16 + gr;
        #pragma unroll
        for (int ni = 0; ni < 8; ni++) {
            const int col = warp_n * 64 + ni * 8 + tc * 2;
            const float2 bb = *(const float2*)(bo + col);
            float2 o0v, o1v;
            o0v.x = acc[mi][ni][0] + bb.x;
            o0v.y = acc[mi][ni][1] + bb.y;
            o1v.x = acc[mi][ni][2] + bb.x;
            o1v.y = acc[mi][ni][3] + bb.y;
            *(float2*)(out + (size_t)orow * OUTC + col) = o0v;
            *(float2*)(out + (size_t)(orow + 8) * OUTC + col) = o1v;
        }
    }
}

// ---------------------------------------------------------------------------
extern "C" void kernel_launch(void* const* d_in, const int* in_sizes, int n_in,
                              void* d_out, int out_size) {
    const float* u  = (const float*)d_in[0];
    // d_in[1] = pos_src -- unused by the reference computation
    const float* Wq = (const float*)d_in[2];
    const float* Wk = (const float*)d_in[3];
    const float* Wv = (const float*)d_in[4];
    const float* Wo = (const float*)d_in[5];
    const float* bo = (const float*)d_in[6];
    float* out = (float*)d_out;

    k_g  <<<dim3(3, NCH, BB), 256>>>(u);
    kA   <<<dim3(CC, BB), 256>>>();
    kB1  <<<dim3(BB * HH, 2, 4), 256>>>(Wk, Wv);
    kB2T <<<dim3(4, BB * HH), 256>>>(Wv, Wq);
    k3c_F<<<dim3(4, 4, BB), 256>>>(Wo);
    k4_mma<<<512, 512>>>(u, bo, out);
}